// round 3
// baseline (speedup 1.0000x reference)
#include <cuda_runtime.h>

#define B_  16
#define C_  256
#define C2_ 128
#define N_  2048
#define BN_EPS 1e-5f

// ---------------- scratch (device globals; no allocation allowed) ----------
__device__ float g_Q [(size_t)B_ * C2_ * N_];           // 16 MB  [b][c2][n]
__device__ float g_Kp[(size_t)B_ * C2_ * N_];           // 16 MB  [b][c2][n]
__device__ float g_V [(size_t)B_ * C_  * N_];           // 32 MB  [b][c][n]
__device__ float g_X2[(size_t)B_ * C_  * N_];           // 32 MB  [b][c][n]
__device__ float g_E [(size_t)B_ * N_  * N_];           // 256 MB [b][n][m]
__device__ float g_D [(size_t)B_ * C_  * N_];           // 32 MB  [b][c][n]
__device__ float g_CS[(size_t)B_ * N_];                 // colsum [b][m]

// ---------------------------------------------------------------------------
// Generic 128x128 tiled SGEMM, K-tile 8, 256 threads, 8x8 microtile,
// double-buffered smem.  C[row,col] = sum_k A(row,k) * B(k,col)  per batch z.
//   ATRANS=false: A is [M,Kdim] row-major
//   ATRANS=true : A is [Kdim,M] row-major (used for E = Q^T K)
// Epilogues:
//   EPI 0: C = acc
//   EPI 1: C = acc + bias[row]
//   EPI 2: C = X2 - acc / (1e-9 + colsum[col])          (D = x2 - x_r)
//   EPI 3: C = relu((acc + bt[row])*inv[row] + shift[row]) + X2   (final out)
// ---------------------------------------------------------------------------
template<int EPI, bool ATRANS>
__global__ __launch_bounds__(256, 2)
void sgemm_k(const float* __restrict__ Ag, const float* __restrict__ Bg,
             float* __restrict__ Cg,
             int M, int Np, int Kdim,
             size_t aB, size_t bB, size_t cB,
             const float* __restrict__ bias,
             const float* __restrict__ x2g,
             const float* __restrict__ csg,
             const float* __restrict__ gga, const float* __restrict__ gbe,
             const float* __restrict__ gme, const float* __restrict__ gva,
             const float* __restrict__ gbt)
{
    __shared__ float As[2][8][128];
    __shared__ float Bs[2][8][128];

    const int bz = blockIdx.z;
    const float* A  = Ag + (size_t)bz * aB;
    const float* Bm = Bg + (size_t)bz * bB;
    float*       Cp = Cg + (size_t)bz * cB;

    const int mBase = blockIdx.y * 128;
    const int nBase = blockIdx.x * 128;
    const int tid = threadIdx.x;
    const int tx = tid & 15, ty = tid >> 4;

    int ar, ac;
    if (ATRANS) { ar = tid >> 5; ac = (tid & 31) * 4; }
    else        { ar = tid >> 1; ac = (tid & 1) * 4; }
    const int br = tid >> 5, bc = (tid & 31) * 4;

    float acc[8][8];
    #pragma unroll
    for (int i = 0; i < 8; i++)
        #pragma unroll
        for (int j = 0; j < 8; j++) acc[i][j] = 0.f;

    const int KT = Kdim >> 3;
    float4 aReg, bReg;

    // prologue: tile 0
    if (ATRANS) aReg = *(const float4*)(A + (size_t)ar * M + mBase + ac);
    else        aReg = *(const float4*)(A + (size_t)(mBase + ar) * Kdim + ac);
    bReg = *(const float4*)(Bm + (size_t)br * Np + nBase + bc);
    if (ATRANS) { *(float4*)&As[0][ar][ac] = aReg; }
    else {
        As[0][ac+0][ar] = aReg.x; As[0][ac+1][ar] = aReg.y;
        As[0][ac+2][ar] = aReg.z; As[0][ac+3][ar] = aReg.w;
    }
    *(float4*)&Bs[0][br][bc] = bReg;
    __syncthreads();

    int st = 0;
    for (int kt = 0; kt < KT; ++kt) {
        if (kt + 1 < KT) {
            const int k0 = (kt + 1) << 3;
            if (ATRANS) aReg = *(const float4*)(A + (size_t)(k0 + ar) * M + mBase + ac);
            else        aReg = *(const float4*)(A + (size_t)(mBase + ar) * Kdim + k0 + ac);
            bReg = *(const float4*)(Bm + (size_t)(k0 + br) * Np + nBase + bc);
        }
        #pragma unroll
        for (int k = 0; k < 8; k++) {
            float a[8], bb[8];
            *(float4*)&a[0]  = *(const float4*)&As[st][k][ty * 8];
            *(float4*)&a[4]  = *(const float4*)&As[st][k][ty * 8 + 4];
            *(float4*)&bb[0] = *(const float4*)&Bs[st][k][tx * 8];
            *(float4*)&bb[4] = *(const float4*)&Bs[st][k][tx * 8 + 4];
            #pragma unroll
            for (int i = 0; i < 8; i++)
                #pragma unroll
                for (int j = 0; j < 8; j++)
                    acc[i][j] = fmaf(a[i], bb[j], acc[i][j]);
        }
        if (kt + 1 < KT) {
            st ^= 1;
            if (ATRANS) { *(float4*)&As[st][ar][ac] = aReg; }
            else {
                As[st][ac+0][ar] = aReg.x; As[st][ac+1][ar] = aReg.y;
                As[st][ac+2][ar] = aReg.z; As[st][ac+3][ar] = aReg.w;
            }
            *(float4*)&Bs[st][br][bc] = bReg;
            __syncthreads();
        }
    }

    const int row0 = mBase + ty * 8;
    const int col0 = nBase + tx * 8;

    if (EPI == 0 || EPI == 1) {
        #pragma unroll
        for (int i = 0; i < 8; i++) {
            float bb = (EPI == 1) ? bias[row0 + i] : 0.f;
            float4 o0 = make_float4(acc[i][0]+bb, acc[i][1]+bb, acc[i][2]+bb, acc[i][3]+bb);
            float4 o1 = make_float4(acc[i][4]+bb, acc[i][5]+bb, acc[i][6]+bb, acc[i][7]+bb);
            size_t off = (size_t)(row0 + i) * Np + col0;
            *(float4*)(Cp + off)     = o0;
            *(float4*)(Cp + off + 4) = o1;
        }
    } else if (EPI == 2) {
        const float* X2 = x2g + (size_t)bz * cB;
        const float* cs = csg + (size_t)bz * Np;
        float inv[8];
        #pragma unroll
        for (int j = 0; j < 8; j++) inv[j] = 1.f / (1e-9f + cs[col0 + j]);
        #pragma unroll
        for (int i = 0; i < 8; i++) {
            size_t off = (size_t)(row0 + i) * Np + col0;
            float4 x0 = *(const float4*)(X2 + off);
            float4 x1 = *(const float4*)(X2 + off + 4);
            float4 o0 = make_float4(x0.x - acc[i][0]*inv[0], x0.y - acc[i][1]*inv[1],
                                    x0.z - acc[i][2]*inv[2], x0.w - acc[i][3]*inv[3]);
            float4 o1 = make_float4(x1.x - acc[i][4]*inv[4], x1.y - acc[i][5]*inv[5],
                                    x1.z - acc[i][6]*inv[6], x1.w - acc[i][7]*inv[7]);
            *(float4*)(Cp + off)     = o0;
            *(float4*)(Cp + off + 4) = o1;
        }
    } else { // EPI == 3
        const float* X2 = x2g + (size_t)bz * cB;
        #pragma unroll
        for (int i = 0; i < 8; i++) {
            const int r = row0 + i;
            const float iv = gga[r] * rsqrtf(gva[r] + BN_EPS);
            const float sh = gbe[r] - gme[r] * iv;
            const float bo = gbt[r];
            size_t off = (size_t)r * Np + col0;
            float4 x0 = *(const float4*)(X2 + off);
            float4 x1 = *(const float4*)(X2 + off + 4);
            float4 o0, o1;
            o0.x = fmaxf((acc[i][0]+bo)*iv + sh, 0.f) + x0.x;
            o0.y = fmaxf((acc[i][1]+bo)*iv + sh, 0.f) + x0.y;
            o0.z = fmaxf((acc[i][2]+bo)*iv + sh, 0.f) + x0.z;
            o0.w = fmaxf((acc[i][3]+bo)*iv + sh, 0.f) + x0.w;
            o1.x = fmaxf((acc[i][4]+bo)*iv + sh, 0.f) + x1.x;
            o1.y = fmaxf((acc[i][5]+bo)*iv + sh, 0.f) + x1.y;
            o1.z = fmaxf((acc[i][6]+bo)*iv + sh, 0.f) + x1.z;
            o1.w = fmaxf((acc[i][7]+bo)*iv + sh, 0.f) + x1.w;
            *(float4*)(Cp + off)     = o0;
            *(float4*)(Cp + off + 4) = o1;
        }
    }
}

// ---------------------------------------------------------------------------
// Row softmax in-place: one block per (b, n) row of 2048 fp32 (registers).
// ---------------------------------------------------------------------------
__global__ __launch_bounds__(256)
void softmax_k(float* __restrict__ E)
{
    __shared__ float redm[8];
    __shared__ float reds[8];
    const size_t row = blockIdx.x;
    float4* p = reinterpret_cast<float4*>(E + row * (size_t)N_);
    const int tid = threadIdx.x;

    float4 v0 = p[tid];
    float4 v1 = p[tid + 256];

    float mx = fmaxf(fmaxf(fmaxf(v0.x, v0.y), fmaxf(v0.z, v0.w)),
                     fmaxf(fmaxf(v1.x, v1.y), fmaxf(v1.z, v1.w)));
    #pragma unroll
    for (int o = 16; o > 0; o >>= 1)
        mx = fmaxf(mx, __shfl_xor_sync(0xffffffffu, mx, o));
    if ((tid & 31) == 0) redm[tid >> 5] = mx;
    __syncthreads();
    mx = fmaxf(fmaxf(fmaxf(redm[0], redm[1]), fmaxf(redm[2], redm[3])),
               fmaxf(fmaxf(redm[4], redm[5]), fmaxf(redm[6], redm[7])));

    v0.x = __expf(v0.x - mx); v0.y = __expf(v0.y - mx);
    v0.z = __expf(v0.z - mx); v0.w = __expf(v0.w - mx);
    v1.x = __expf(v1.x - mx); v1.y = __expf(v1.y - mx);
    v1.z = __expf(v1.z - mx); v1.w = __expf(v1.w - mx);

    float s = (v0.x + v0.y + v0.z + v0.w) + (v1.x + v1.y + v1.z + v1.w);
    #pragma unroll
    for (int o = 16; o > 0; o >>= 1)
        s += __shfl_xor_sync(0xffffffffu, s, o);
    if ((tid & 31) == 0) reds[tid >> 5] = s;
    __syncthreads();
    s = (reds[0] + reds[1] + reds[2] + reds[3]) +
        (reds[4] + reds[5] + reds[6] + reds[7]);

    const float inv = 1.f / s;
    v0.x *= inv; v0.y *= inv; v0.z *= inv; v0.w *= inv;
    v1.x *= inv; v1.y *= inv; v1.z *= inv; v1.w *= inv;
    p[tid]       = v0;
    p[tid + 256] = v1;
}

__global__ void zero_k(float* __restrict__ p, int n)
{
    int i = blockIdx.x * blockDim.x + threadIdx.x;
    if (i < n) p[i] = 0.f;
}

// colsum[b][m] += sum over a 128-row chunk of S[b][n][m]
__global__ __launch_bounds__(256)
void colsum_k(const float* __restrict__ S, float* __restrict__ cs)
{
    const int b  = blockIdx.z;
    const int m  = blockIdx.x * 256 + threadIdx.x;
    const int n0 = blockIdx.y * 128;
    const float* p = S + (size_t)b * N_ * N_ + (size_t)n0 * N_ + m;
    float s0 = 0.f, s1 = 0.f, s2 = 0.f, s3 = 0.f;
    #pragma unroll 4
    for (int n = 0; n < 128; n += 4) {
        s0 += p[(size_t)(n + 0) * N_];
        s1 += p[(size_t)(n + 1) * N_];
        s2 += p[(size_t)(n + 2) * N_];
        s3 += p[(size_t)(n + 3) * N_];
    }
    atomicAdd(&cs[b * N_ + m], (s0 + s1) + (s2 + s3));
}

// ---------------------------------------------------------------------------
extern "C" void kernel_launch(void* const* d_in, const int* in_sizes, int n_in,
                              void* d_out, int out_size)
{
    const float* q  = (const float*)d_in[0];
    const float* x  = (const float*)d_in[1];
    const float* Wq = (const float*)d_in[2];
    const float* Wk = (const float*)d_in[3];
    const float* Wv = (const float*)d_in[4];
    const float* bv = (const float*)d_in[5];
    const float* Wt = (const float*)d_in[6];
    const float* bt = (const float*)d_in[7];
    const float* ga = (const float*)d_in[8];
    const float* be = (const float*)d_in[9];
    const float* rm = (const float*)d_in[10];
    const float* rv = (const float*)d_in[11];
    float* out = (float*)d_out;

    float *pQ, *pK, *pV, *pX2, *pE, *pD, *pCS;
    cudaGetSymbolAddress((void**)&pQ,  g_Q);
    cudaGetSymbolAddress((void**)&pK,  g_Kp);
    cudaGetSymbolAddress((void**)&pV,  g_V);
    cudaGetSymbolAddress((void**)&pX2, g_X2);
    cudaGetSymbolAddress((void**)&pE,  g_E);
    cudaGetSymbolAddress((void**)&pD,  g_D);
    cudaGetSymbolAddress((void**)&pCS, g_CS);

    const size_t s2 = (size_t)C2_ * N_;   // 128*2048
    const size_t sc = (size_t)C_  * N_;   // 256*2048
    const size_t se = (size_t)N_  * N_;   // 2048*2048
    dim3 blk(256);

    // Q = Wq @ q[b]            [128,2048]
    sgemm_k<0,false><<<dim3(16,1,B_), blk>>>(Wq, q, pQ, C2_, N_, C2_,
        0, s2, s2, nullptr, nullptr, nullptr, nullptr, nullptr, nullptr, nullptr, nullptr);
    // K = Wk @ x[b]            [128,2048]
    sgemm_k<0,false><<<dim3(16,1,B_), blk>>>(Wk, x, pK, C2_, N_, C2_,
        0, s2, s2, nullptr, nullptr, nullptr, nullptr, nullptr, nullptr, nullptr, nullptr);
    // V = Wv @ q[b] + bv       [256,2048]
    sgemm_k<1,false><<<dim3(16,2,B_), blk>>>(Wv, q, pV, C_, N_, C2_,
        0, s2, sc, bv, nullptr, nullptr, nullptr, nullptr, nullptr, nullptr, nullptr);
    // X2 = Wv @ x[b] + bv      [256,2048]
    sgemm_k<1,false><<<dim3(16,2,B_), blk>>>(Wv, x, pX2, C_, N_, C2_,
        0, s2, sc, bv, nullptr, nullptr, nullptr, nullptr, nullptr, nullptr, nullptr);
    // E = Q^T K                [2048,2048] per batch
    sgemm_k<0,true><<<dim3(16,16,B_), blk>>>(pQ, pK, pE, N_, N_, C2_,
        s2, s2, se, nullptr, nullptr, nullptr, nullptr, nullptr, nullptr, nullptr, nullptr);
    // row softmax in-place
    softmax_k<<<B_ * N_, 256>>>(pE);
    // column sums
    zero_k<<<(B_ * N_ + 255) / 256, 256>>>(pCS, B_ * N_);
    colsum_k<<<dim3(N_ / 256, 16, B_), 256>>>(pE, pCS);
    // D = X2 - (V @ S) / (1e-9 + colsum)
    sgemm_k<2,false><<<dim3(16,2,B_), blk>>>(pV, pE, pD, C_, N_, N_,
        sc, se, sc, nullptr, pX2, pCS, nullptr, nullptr, nullptr, nullptr, nullptr);
    // out = relu(bn(Wt @ D + bt)) + X2
    sgemm_k<3,false><<<dim3(16,2,B_), blk>>>(Wt, pD, out, C_, N_, C_,
        0, sc, sc, nullptr, pX2, nullptr, ga, be, rm, rv, bt);
}

// round 5
// speedup vs baseline: 1.8302x; 1.8302x over previous
#include <cuda_runtime.h>
#include <cuda_bf16.h>
#include <cstdint>

#define B_  16
#define C_  256
#define C2_ 128
#define N_  2048
#define BN_EPS 1e-5f
typedef __nv_bfloat16 bf16;

// ---------------- scratch (device globals) ---------------------------------
__device__ __align__(128) bf16 g_qTh[(size_t)B_*N_*C2_], g_qTl[(size_t)B_*N_*C2_];
__device__ __align__(128) bf16 g_xTh[(size_t)B_*N_*C2_], g_xTl[(size_t)B_*N_*C2_];
__device__ __align__(128) bf16 g_Wqh[C2_*C2_], g_Wql[C2_*C2_];
__device__ __align__(128) bf16 g_Wkh[C2_*C2_], g_Wkl[C2_*C2_];
__device__ __align__(128) bf16 g_Wvh[C_*C2_],  g_Wvl[C_*C2_];
__device__ __align__(128) bf16 g_Wth[C_*C_],   g_Wtl[C_*C_];
__device__ __align__(128) bf16 g_QTh[(size_t)B_*N_*C2_], g_QTl[(size_t)B_*N_*C2_];
__device__ __align__(128) bf16 g_KTh[(size_t)B_*N_*C2_], g_KTl[(size_t)B_*N_*C2_];
__device__ __align__(128) bf16 g_Vh[(size_t)B_*C_*N_],   g_Vl[(size_t)B_*C_*N_];
__device__ __align__(128) float g_X2T[(size_t)B_*N_*C_];
__device__ __align__(128) float g_X2f[(size_t)B_*C_*N_];
__device__ __align__(128) float g_E[(size_t)B_*N_*N_];
__device__ __align__(128) float g_rmax[(size_t)B_*N_], g_rinv[(size_t)B_*N_];
__device__ __align__(128) float g_cs[(size_t)B_*N_];
__device__ __align__(128) bf16 g_STh[(size_t)B_*N_*N_], g_STl[(size_t)B_*N_*N_];
__device__ __align__(128) float g_XR[(size_t)B_*N_*C_];
__device__ __align__(128) bf16 g_D2h[(size_t)B_*N_*C_], g_D2l[(size_t)B_*N_*C_];

// ---------------- helpers --------------------------------------------------
__device__ __forceinline__ uint32_t smem_u32(const void* p) {
    uint32_t a;
    asm("{ .reg .u64 t; cvta.to.shared.u64 t, %1; cvt.u32.u64 %0, t; }" : "=r"(a) : "l"(p));
    return a;
}
#define SWZ64(x) ((x) ^ (((x) >> 3) & 0x30))
#define CP_COMMIT() asm volatile("cp.async.commit_group;" ::: "memory")
#define CP_WAIT1()  asm volatile("cp.async.wait_group 1;" ::: "memory")
#define CP_WAIT0()  asm volatile("cp.async.wait_group 0;" ::: "memory")

__device__ __forceinline__ void cp16(uint32_t dst, const void* src) {
    asm volatile("cp.async.cg.shared.global [%0], [%1], 16;" :: "r"(dst), "l"(src));
}
__device__ __forceinline__ void ldsm4(uint32_t* r, uint32_t a) {
    asm volatile("ldmatrix.sync.aligned.m8n8.x4.shared.b16 {%0,%1,%2,%3}, [%4];"
        : "=r"(r[0]), "=r"(r[1]), "=r"(r[2]), "=r"(r[3]) : "r"(a));
}
__device__ __forceinline__ void ldsm2(uint32_t* r, uint32_t a) {
    asm volatile("ldmatrix.sync.aligned.m8n8.x2.shared.b16 {%0,%1}, [%2];"
        : "=r"(r[0]), "=r"(r[1]) : "r"(a));
}
__device__ __forceinline__ void mma16816(float* d, const uint32_t* a, const uint32_t* b) {
    asm volatile("mma.sync.aligned.m16n8k16.row.col.f32.bf16.bf16.f32 "
        "{%0,%1,%2,%3}, {%4,%5,%6,%7}, {%8,%9}, {%0,%1,%2,%3};"
        : "+f"(d[0]), "+f"(d[1]), "+f"(d[2]), "+f"(d[3])
        : "r"(a[0]), "r"(a[1]), "r"(a[2]), "r"(a[3]), "r"(b[0]), "r"(b[1]));
}
__device__ __forceinline__ uint32_t pk(float a, float b) {
    __nv_bfloat162 t = __floats2bfloat162_rn(a, b);
    return *reinterpret_cast<uint32_t*>(&t);
}

// ---------------- split-bf16 warp-MMA GEMM ---------------------------------
// C[M, Np] = (Ah+Al)[M,K] * (Bh+Bl)[Np,K]^T, both K-major bf16 hi/lo.
// Tile 128x128, Kc=32, double-buffered cp.async, 8 warps of 64x32.
// EPI: 0 f32 | 1 f32+bias[col] | 2 f32+bias[row] | 3 split hi/lo
//      4 split+bias[row] | 5 final: relu(bn(acc+bt))+x2f
template<int EPI>
__global__ __launch_bounds__(256, 1)
void mmk(const bf16* __restrict__ Ah, const bf16* __restrict__ Al,
         const bf16* __restrict__ Bh, const bf16* __restrict__ Bl,
         float* __restrict__ Cf, bf16* __restrict__ Ch, bf16* __restrict__ Cl,
         int Kdim, size_t sA, size_t sB, size_t sC, int ldC,
         const float* __restrict__ bias, const float* __restrict__ x2f,
         const float* __restrict__ ga, const float* __restrict__ be,
         const float* __restrict__ rm, const float* __restrict__ rv,
         const float* __restrict__ bt)
{
    extern __shared__ __align__(128) char smem[];
    const uint32_t sb = smem_u32(smem);
    const int tid = threadIdx.x, wid = tid >> 5, lane = tid & 31;
    const int wm = wid & 1, wn = wid >> 1;
    const int bz = blockIdx.z;
    const size_t rb = (size_t)Kdim * 2;

    const char* gAh = (const char*)(Ah + bz * sA) + (size_t)(blockIdx.y * 128) * rb;
    const char* gAl = (const char*)(Al + bz * sA) + (size_t)(blockIdx.y * 128) * rb;
    const char* gBh = (const char*)(Bh + bz * sB) + (size_t)(blockIdx.x * 128) * rb;
    const char* gBl = (const char*)(Bl + bz * sB) + (size_t)(blockIdx.x * 128) * rb;

    float acc[4][4][4];
    #pragma unroll
    for (int i = 0; i < 4; i++)
        #pragma unroll
        for (int j = 0; j < 4; j++)
            #pragma unroll
            for (int k = 0; k < 4; k++) acc[i][j][k] = 0.f;

    const int NC = Kdim >> 5;

    auto load_stage = [&](int s, int chunk) {
        const uint32_t base = sb + s * 32768;
        const size_t cb = (size_t)chunk * 64;
        #pragma unroll
        for (int j = 0; j < 2; j++) {
            int idx = j * 256 + tid;
            int r = idx >> 2, c = (idx & 3) * 16;
            uint32_t off = SWZ64(r * 64 + c);
            size_t go = (size_t)r * rb + cb + c;
            cp16(base + off,         gAh + go);
            cp16(base + 8192 + off,  gAl + go);
            cp16(base + 16384 + off, gBh + go);
            cp16(base + 24576 + off, gBl + go);
        }
        CP_COMMIT();
    };

    load_stage(0, 0);
    load_stage(1, 1);

    for (int i = 0; i < NC; i++) {
        const int s = i & 1;
        if (i + 1 < NC) { CP_WAIT1(); } else { CP_WAIT0(); }
        __syncthreads();
        const uint32_t aB = sb + s * 32768, bB = aB + 16384;
        #pragma unroll
        for (int ks = 0; ks < 2; ks++) {
            uint32_t ah[4][4], al[4][4], bh[4][2], bl[4][2];
            #pragma unroll
            for (int ma = 0; ma < 4; ma++) {
                int row = wm * 64 + ma * 16 + (lane & 15);
                uint32_t off = SWZ64(row * 64 + ks * 32 + ((lane >> 4) * 16));
                ldsm4(ah[ma], aB + off);
                ldsm4(al[ma], aB + 8192 + off);
            }
            #pragma unroll
            for (int na = 0; na < 4; na++) {
                int row = wn * 32 + na * 8 + (lane & 7);
                uint32_t off = SWZ64(row * 64 + ks * 32 + (((lane >> 3) & 1) * 16));
                ldsm2(bh[na], bB + off);
                ldsm2(bl[na], bB + 8192 + off);
            }
            #pragma unroll
            for (int ma = 0; ma < 4; ma++)
                #pragma unroll
                for (int na = 0; na < 4; na++) {
                    mma16816(acc[ma][na], ah[ma], bh[na]);
                    mma16816(acc[ma][na], ah[ma], bl[na]);
                    mma16816(acc[ma][na], al[ma], bh[na]);
                }
        }
        if (i + 2 < NC) { __syncthreads(); load_stage(s, i + 2); }
    }

    // ---------------- epilogue ----------------
    const int g = lane >> 2, t = lane & 3;
    const int mB = blockIdx.y * 128 + wm * 64;
    const int nB = blockIdx.x * 128 + wn * 32;
    float* Cfb = (EPI <= 2 || EPI == 5) ? Cf + bz * sC : nullptr;
    bf16* Chb = (EPI == 3 || EPI == 4) ? Ch + bz * sC : nullptr;
    bf16* Clb = (EPI == 3 || EPI == 4) ? Cl + bz * sC : nullptr;
    const float* x2b = (EPI == 5) ? x2f + bz * sC : nullptr;

    #pragma unroll
    for (int ma = 0; ma < 4; ma++) {
        const int r0 = mB + ma * 16 + g;
        const int r1 = r0 + 8;
        float p0 = 0.f, p1 = 0.f, iv0 = 0.f, sh0 = 0.f, bo0 = 0.f;
        float iv1 = 0.f, sh1 = 0.f, bo1 = 0.f;
        if (EPI == 2 || EPI == 4) { p0 = bias[r0]; p1 = bias[r1]; }
        if (EPI == 5) {
            iv0 = ga[r0] * rsqrtf(rv[r0] + BN_EPS);
            sh0 = be[r0] - rm[r0] * iv0; bo0 = bt[r0];
            iv1 = ga[r1] * rsqrtf(rv[r1] + BN_EPS);
            sh1 = be[r1] - rm[r1] * iv1; bo1 = bt[r1];
        }
        #pragma unroll
        for (int na = 0; na < 4; na++) {
            const int c0 = nB + na * 8 + 2 * t;
            const float* a = acc[ma][na];
            const size_t o0 = (size_t)r0 * ldC + c0;
            const size_t o1 = (size_t)r1 * ldC + c0;
            if (EPI == 0) {
                *(float2*)(Cfb + o0) = make_float2(a[0], a[1]);
                *(float2*)(Cfb + o1) = make_float2(a[2], a[3]);
            } else if (EPI == 1) {
                float b0 = bias[c0], b1 = bias[c0 + 1];
                *(float2*)(Cfb + o0) = make_float2(a[0] + b0, a[1] + b1);
                *(float2*)(Cfb + o1) = make_float2(a[2] + b0, a[3] + b1);
            } else if (EPI == 2) {
                *(float2*)(Cfb + o0) = make_float2(a[0] + p0, a[1] + p0);
                *(float2*)(Cfb + o1) = make_float2(a[2] + p1, a[3] + p1);
            } else if (EPI == 3 || EPI == 4) {
                float v0 = a[0], v1 = a[1], v2 = a[2], v3 = a[3];
                if (EPI == 4) { v0 += p0; v1 += p0; v2 += p1; v3 += p1; }
                float h0 = __bfloat162float(__float2bfloat16(v0));
                float h1 = __bfloat162float(__float2bfloat16(v1));
                float h2 = __bfloat162float(__float2bfloat16(v2));
                float h3 = __bfloat162float(__float2bfloat16(v3));
                *(uint32_t*)(Chb + o0) = pk(h0, h1);
                *(uint32_t*)(Clb + o0) = pk(v0 - h0, v1 - h1);
                *(uint32_t*)(Chb + o1) = pk(h2, h3);
                *(uint32_t*)(Clb + o1) = pk(v2 - h2, v3 - h3);
            } else { // EPI 5
                float2 x0 = *(const float2*)(x2b + o0);
                float2 x1 = *(const float2*)(x2b + o1);
                float2 w0, w1;
                w0.x = fmaxf((a[0] + bo0) * iv0 + sh0, 0.f) + x0.x;
                w0.y = fmaxf((a[1] + bo0) * iv0 + sh0, 0.f) + x0.y;
                w1.x = fmaxf((a[2] + bo1) * iv1 + sh1, 0.f) + x1.x;
                w1.y = fmaxf((a[3] + bo1) * iv1 + sh1, 0.f) + x1.y;
                *(float2*)(Cfb + o0) = w0;
                *(float2*)(Cfb + o1) = w1;
            }
        }
    }
}

// ---------------- aux kernels ----------------------------------------------
__global__ void split_w(const float* __restrict__ w, bf16* __restrict__ h,
                        bf16* __restrict__ l, int n)
{
    int i = blockIdx.x * 256 + threadIdx.x;
    if (i < n) {
        float v = w[i];
        bf16 hv = __float2bfloat16(v);
        h[i] = hv;
        l[i] = __float2bfloat16(v - __bfloat162float(hv));
    }
}

__global__ void tsplit(const float* __restrict__ in, bf16* __restrict__ oh,
                       bf16* __restrict__ ol)
{
    __shared__ float sm[32][33];
    const int b = blockIdx.z;
    const int n0 = blockIdx.x * 32, c0 = blockIdx.y * 32;
    const int r = threadIdx.x >> 5, c = threadIdx.x & 31;
    const float* ip = in + (size_t)b * C2_ * N_;
    #pragma unroll
    for (int k = 0; k < 4; k++)
        sm[r + 8*k][c] = ip[(size_t)(c0 + r + 8*k) * N_ + n0 + c];
    __syncthreads();
    bf16* oph = oh + (size_t)b * N_ * C2_;
    bf16* opl = ol + (size_t)b * N_ * C2_;
    #pragma unroll
    for (int k = 0; k < 4; k++) {
        float v = sm[c][r + 8*k];
        bf16 hv = __float2bfloat16(v);
        size_t o = (size_t)(n0 + r + 8*k) * C2_ + c0 + c;
        oph[o] = hv;
        opl[o] = __float2bfloat16(v - __bfloat162float(hv));
    }
}

__global__ __launch_bounds__(256)
void rowstat(const float* __restrict__ E, float* __restrict__ rmax, float* __restrict__ rinv)
{
    __shared__ float red[8];
    const size_t row = blockIdx.x;
    const float4* p = (const float4*)(E + row * (size_t)N_);
    const int tid = threadIdx.x;
    float4 v0 = p[tid], v1 = p[tid + 256];
    float mx = fmaxf(fmaxf(fmaxf(v0.x,v0.y),fmaxf(v0.z,v0.w)),
                     fmaxf(fmaxf(v1.x,v1.y),fmaxf(v1.z,v1.w)));
    #pragma unroll
    for (int o = 16; o > 0; o >>= 1) mx = fmaxf(mx, __shfl_xor_sync(~0u, mx, o));
    if ((tid & 31) == 0) red[tid >> 5] = mx;
    __syncthreads();
    mx = fmaxf(fmaxf(fmaxf(red[0],red[1]),fmaxf(red[2],red[3])),
               fmaxf(fmaxf(red[4],red[5]),fmaxf(red[6],red[7])));
    float s = __expf(v0.x-mx)+__expf(v0.y-mx)+__expf(v0.z-mx)+__expf(v0.w-mx)
            + __expf(v1.x-mx)+__expf(v1.y-mx)+__expf(v1.z-mx)+__expf(v1.w-mx);
    #pragma unroll
    for (int o = 16; o > 0; o >>= 1) s += __shfl_xor_sync(~0u, s, o);
    __syncthreads();
    if ((tid & 31) == 0) red[tid >> 5] = s;
    __syncthreads();
    if (tid == 0) {
        s = (red[0]+red[1]+red[2]+red[3])+(red[4]+red[5]+red[6]+red[7]);
        rmax[row] = mx;
        rinv[row] = 1.f / s;
    }
}

__global__ void zero_k(float* p, int n)
{
    int i = blockIdx.x * 256 + threadIdx.x;
    if (i < n) p[i] = 0.f;
}

__global__ __launch_bounds__(256)
void texp(const float* __restrict__ E, const float* __restrict__ rmax,
          const float* __restrict__ rinv, bf16* __restrict__ sth,
          bf16* __restrict__ stl, float* __restrict__ cs)
{
    __shared__ float sm[32][33];
    const int b = blockIdx.z;
    const int n0 = blockIdx.x * 32, m0 = blockIdx.y * 32;
    const int r = threadIdx.x >> 5, c = threadIdx.x & 31;
    const float* ep = E + (size_t)b * N_ * N_;
    const float* mxp = rmax + (size_t)b * N_;
    const float* ivp = rinv + (size_t)b * N_;
    #pragma unroll
    for (int k = 0; k < 4; k++) {
        int n = n0 + r + 8*k;
        sm[r + 8*k][c] = __expf(ep[(size_t)n * N_ + m0 + c] - mxp[n]) * ivp[n];
    }
    __syncthreads();
    if (threadIdx.x < 32) {
        float s = 0.f;
        #pragma unroll
        for (int k = 0; k < 32; k++) s += sm[k][threadIdx.x];
        atomicAdd(&cs[(size_t)b * N_ + m0 + threadIdx.x], s);
    }
    bf16* oh = sth + (size_t)b * N_ * N_;
    bf16* ol = stl + (size_t)b * N_ * N_;
    #pragma unroll
    for (int k = 0; k < 4; k++) {
        float v = sm[c][r + 8*k];
        bf16 hv = __float2bfloat16(v);
        size_t o = (size_t)(m0 + r + 8*k) * N_ + n0 + c;
        oh[o] = hv;
        ol[o] = __float2bfloat16(v - __bfloat162float(hv));
    }
}

__global__ void d2k(const float* __restrict__ x2t, const float* __restrict__ xr,
                    const float* __restrict__ cs, bf16* __restrict__ dh,
                    bf16* __restrict__ dl)
{
    size_t i = (size_t)blockIdx.x * 256 + threadIdx.x;
    size_t row = i >> 8;
    float inv = 1.f / (1e-9f + cs[row]);
    float v = x2t[i] - xr[i] * inv;
    bf16 hv = __float2bfloat16(v);
    dh[i] = hv;
    dl[i] = __float2bfloat16(v - __bfloat162float(hv));
}

// ---------------- launcher -------------------------------------------------
extern "C" void kernel_launch(void* const* d_in, const int* in_sizes, int n_in,
                              void* d_out, int out_size)
{
    const float* q  = (const float*)d_in[0];
    const float* x  = (const float*)d_in[1];
    const float* Wq = (const float*)d_in[2];
    const float* Wk = (const float*)d_in[3];
    const float* Wv = (const float*)d_in[4];
    const float* bv = (const float*)d_in[5];
    const float* Wt = (const float*)d_in[6];
    const float* bt = (const float*)d_in[7];
    const float* ga = (const float*)d_in[8];
    const float* be = (const float*)d_in[9];
    const float* rm = (const float*)d_in[10];
    const float* rv = (const float*)d_in[11];
    float* out = (float*)d_out;

    #define SYM(T, p, s) T* p; cudaGetSymbolAddress((void**)&p, s)
    SYM(bf16, qTh, g_qTh); SYM(bf16, qTl, g_qTl);
    SYM(bf16, xTh, g_xTh); SYM(bf16, xTl, g_xTl);
    SYM(bf16, Wqh, g_Wqh); SYM(bf16, Wql, g_Wql);
    SYM(bf16, Wkh, g_Wkh); SYM(bf16, Wkl, g_Wkl);
    SYM(bf16, Wvh, g_Wvh); SYM(bf16, Wvl, g_Wvl);
    SYM(bf16, Wth, g_Wth); SYM(bf16, Wtl, g_Wtl);
    SYM(bf16, QTh, g_QTh); SYM(bf16, QTl, g_QTl);
    SYM(bf16, KTh, g_KTh); SYM(bf16, KTl, g_KTl);
    SYM(bf16, Vh,  g_Vh);  SYM(bf16, Vl,  g_Vl);
    SYM(float, X2T, g_X2T); SYM(float, X2f, g_X2f); SYM(float, E, g_E);
    SYM(float, rmx, g_rmax); SYM(float, riv, g_rinv); SYM(float, cs, g_cs);
    SYM(bf16, STh, g_STh); SYM(bf16, STl, g_STl);
    SYM(float, XR, g_XR);
    SYM(bf16, D2h, g_D2h); SYM(bf16, D2l, g_D2l);
    #undef SYM

    const int SMB = 65536;
    cudaFuncSetAttribute(mmk<0>, cudaFuncAttributeMaxDynamicSharedMemorySize, SMB);
    cudaFuncSetAttribute(mmk<1>, cudaFuncAttributeMaxDynamicSharedMemorySize, SMB);
    cudaFuncSetAttribute(mmk<2>, cudaFuncAttributeMaxDynamicSharedMemorySize, SMB);
    cudaFuncSetAttribute(mmk<3>, cudaFuncAttributeMaxDynamicSharedMemorySize, SMB);
    cudaFuncSetAttribute(mmk<4>, cudaFuncAttributeMaxDynamicSharedMemorySize, SMB);
    cudaFuncSetAttribute(mmk<5>, cudaFuncAttributeMaxDynamicSharedMemorySize, SMB);

    const size_t s2 = (size_t)N_ * C2_;
    const size_t sv = (size_t)C_ * N_;
    const size_t sx = (size_t)N_ * C_;
    const size_t se = (size_t)N_ * N_;

    split_w<<<(C2_*C2_+255)/256, 256>>>(Wq, Wqh, Wql, C2_*C2_);
    split_w<<<(C2_*C2_+255)/256, 256>>>(Wk, Wkh, Wkl, C2_*C2_);
    split_w<<<(C_*C2_+255)/256, 256>>>(Wv, Wvh, Wvl, C_*C2_);
    split_w<<<(C_*C_+255)/256, 256>>>(Wt, Wth, Wtl, C_*C_);
    tsplit<<<dim3(N_/32, C2_/32, B_), 256>>>(q, qTh, qTl);
    tsplit<<<dim3(N_/32, C2_/32, B_), 256>>>(x, xTh, xTl);

    // QT[n][o] = qT*Wq^T   (M=2048, Np=128, K=128) -> split
    mmk<3><<<dim3(1,16,B_), 256, SMB>>>(qTh, qTl, Wqh, Wql, nullptr, QTh, QTl,
        C2_, s2, 0, s2, C2_, nullptr, nullptr, nullptr, nullptr, nullptr, nullptr, nullptr);
    // KT[m][o] = xT*Wk^T
    mmk<3><<<dim3(1,16,B_), 256, SMB>>>(xTh, xTl, Wkh, Wkl, nullptr, KTh, KTl,
        C2_, s2, 0, s2, C2_, nullptr, nullptr, nullptr, nullptr, nullptr, nullptr, nullptr);
    // V[c][n] = Wv*q + bv[row] -> split    (M=256, Np=2048, K=128)
    mmk<4><<<dim3(16,2,B_), 256, SMB>>>(Wvh, Wvl, qTh, qTl, nullptr, Vh, Vl,
        C2_, 0, s2, sv, N_, bv, nullptr, nullptr, nullptr, nullptr, nullptr, nullptr);
    // X2T[n][c] = xT*Wv^T + bv[col]        (M=2048, Np=256, K=128)
    mmk<1><<<dim3(2,16,B_), 256, SMB>>>(xTh, xTl, Wvh, Wvl, X2T, nullptr, nullptr,
        C2_, s2, 0, sx, C_, bv, nullptr, nullptr, nullptr, nullptr, nullptr, nullptr);
    // X2f[c][n] = Wv*x + bv[row]           (M=256, Np=2048, K=128)
    mmk<2><<<dim3(16,2,B_), 256, SMB>>>(Wvh, Wvl, xTh, xTl, X2f, nullptr, nullptr,
        C2_, 0, s2, sv, N_, bv, nullptr, nullptr, nullptr, nullptr, nullptr, nullptr);
    // E[n][m] = QT*KT^T                    (M=2048, Np=2048, K=128)
    mmk<0><<<dim3(16,16,B_), 256, SMB>>>(QTh, QTl, KTh, KTl, E, nullptr, nullptr,
        C2_, s2, s2, se, N_, nullptr, nullptr, nullptr, nullptr, nullptr, nullptr, nullptr);
    // softmax stats, S^T split + colsum
    rowstat<<<B_*N_, 256>>>(E, rmx, riv);
    zero_k<<<(B_*N_+255)/256, 256>>>(cs, B_*N_);
    texp<<<dim3(N_/32, N_/32, B_), 256>>>(E, rmx, riv, STh, STl, cs);
    // XR[m][c] = ST*V^T                    (M=2048, Np=256, K=2048)
    mmk<0><<<dim3(2,16,B_), 256, SMB>>>(STh, STl, Vh, Vl, XR, nullptr, nullptr,
        N_, se, sv, sx, C_, nullptr, nullptr, nullptr, nullptr, nullptr, nullptr, nullptr);
    // D2[n][cin] = X2T - XR/colsum -> split
    d2k<<<(int)((size_t)B_*N_*C_/256), 256>>>(X2T, XR, cs, D2h, D2l);
    // out[c][n] = relu(bn(Wt*D2 + bt)) + X2f   (M=256, Np=2048, K=256)
    mmk<5><<<dim3(16,2,B_), 256, SMB>>>(Wth, Wtl, D2h, D2l, out, nullptr, nullptr,
        C_, 0, sx, sv, N_, nullptr, X2f, ga, be, rm, rv, bt);
}

// round 6
// speedup vs baseline: 1.9405x; 1.0602x over previous
#include <cuda_runtime.h>
#include <cuda_bf16.h>
#include <cstdint>

#define B_  16
#define C_  256
#define C2_ 128
#define N_  2048
#define BN_EPS 1e-5f
typedef __nv_bfloat16 bf16;

// ---------------- scratch (device globals) ---------------------------------
__device__ __align__(128) bf16 g_qTh[(size_t)B_*N_*C2_], g_qTl[(size_t)B_*N_*C2_];
__device__ __align__(128) bf16 g_xTh[(size_t)B_*N_*C2_], g_xTl[(size_t)B_*N_*C2_];
__device__ __align__(128) bf16 g_Wqh[C2_*C2_], g_Wql[C2_*C2_];
__device__ __align__(128) bf16 g_Wkh[C2_*C2_], g_Wkl[C2_*C2_];
__device__ __align__(128) bf16 g_Wvh[C_*C2_],  g_Wvl[C_*C2_];
__device__ __align__(128) bf16 g_Wth[C_*C_],   g_Wtl[C_*C_];
__device__ __align__(128) bf16 g_QTh[(size_t)B_*N_*C2_], g_QTl[(size_t)B_*N_*C2_];
__device__ __align__(128) bf16 g_KTh[(size_t)B_*N_*C2_], g_KTl[(size_t)B_*N_*C2_];
__device__ __align__(128) float g_Vf[(size_t)B_*C_*N_];                 // fp32 V
__device__ __align__(128) bf16 g_Vph[(size_t)B_*C_*N_], g_Vpl[(size_t)B_*C_*N_]; // V' = V*rinv
__device__ __align__(128) float g_X2T[(size_t)B_*N_*C_];
__device__ __align__(128) float g_X2f[(size_t)B_*C_*N_];
__device__ __align__(128) float g_rs[(size_t)B_*N_], g_rinv[(size_t)B_*N_];
__device__ __align__(128) float g_cs[(size_t)B_*N_];
__device__ __align__(128) bf16 g_PTh[(size_t)B_*N_*N_], g_PTl[(size_t)B_*N_*N_];
__device__ __align__(128) bf16 g_D2h[(size_t)B_*N_*C_], g_D2l[(size_t)B_*N_*C_];

// ---------------- helpers --------------------------------------------------
__device__ __forceinline__ uint32_t smem_u32(const void* p) {
    uint32_t a;
    asm("{ .reg .u64 t; cvta.to.shared.u64 t, %1; cvt.u32.u64 %0, t; }" : "=r"(a) : "l"(p));
    return a;
}
#define SWZ64(x) ((x) ^ (((x) >> 3) & 0x30))
#define CP_COMMIT() asm volatile("cp.async.commit_group;" ::: "memory")
#define CP_WAIT1()  asm volatile("cp.async.wait_group 1;" ::: "memory")
#define CP_WAIT0()  asm volatile("cp.async.wait_group 0;" ::: "memory")

__device__ __forceinline__ void cp16(uint32_t dst, const void* src) {
    asm volatile("cp.async.cg.shared.global [%0], [%1], 16;" :: "r"(dst), "l"(src));
}
__device__ __forceinline__ void ldsm4(uint32_t* r, uint32_t a) {
    asm volatile("ldmatrix.sync.aligned.m8n8.x4.shared.b16 {%0,%1,%2,%3}, [%4];"
        : "=r"(r[0]), "=r"(r[1]), "=r"(r[2]), "=r"(r[3]) : "r"(a));
}
__device__ __forceinline__ void ldsm2(uint32_t* r, uint32_t a) {
    asm volatile("ldmatrix.sync.aligned.m8n8.x2.shared.b16 {%0,%1}, [%2];"
        : "=r"(r[0]), "=r"(r[1]) : "r"(a));
}
__device__ __forceinline__ void mma16816(float* d, const uint32_t* a, const uint32_t* b) {
    asm volatile("mma.sync.aligned.m16n8k16.row.col.f32.bf16.bf16.f32 "
        "{%0,%1,%2,%3}, {%4,%5,%6,%7}, {%8,%9}, {%0,%1,%2,%3};"
        : "+f"(d[0]), "+f"(d[1]), "+f"(d[2]), "+f"(d[3])
        : "r"(a[0]), "r"(a[1]), "r"(a[2]), "r"(a[3]), "r"(b[0]), "r"(b[1]));
}
__device__ __forceinline__ uint32_t pk(float a, float b) {
    __nv_bfloat162 t = __floats2bfloat162_rn(a, b);
    return *reinterpret_cast<uint32_t*>(&t);
}

// ---------------- split-bf16 warp-MMA GEMM ---------------------------------
// C[M, Np] = (Ah+Al)[M,K] * (Bh+Bl)[Np,K]^T, both K-major bf16 hi/lo.
// Tile 128x128, Kc=32, double-buffered cp.async, 8 warps of 64x32.
// EPI: 0 f32 | 1 f32+bias[col] | 2 f32+bias[row] | 3 split hi/lo
//      4 split+bias[row] | 5 final relu(bn)+x2 | 6 XR: split(x2t - acc/cs[row])
//      7 E: P=exp(acc), transposed hi/lo store + atomic rowsums
template<int EPI>
__global__ __launch_bounds__(256, 1)
void mmk(const bf16* __restrict__ Ah, const bf16* __restrict__ Al,
         const bf16* __restrict__ Bh, const bf16* __restrict__ Bl,
         float* __restrict__ Cf, bf16* __restrict__ Ch, bf16* __restrict__ Cl,
         int Kdim, size_t sA, size_t sB, size_t sC, int ldC,
         const float* __restrict__ bias, const float* __restrict__ x2f,
         const float* __restrict__ ga, const float* __restrict__ be,
         const float* __restrict__ rm, const float* __restrict__ rv,
         const float* __restrict__ bt, float* __restrict__ rsum)
{
    extern __shared__ __align__(128) char smem[];
    const uint32_t sb = smem_u32(smem);
    const int tid = threadIdx.x, wid = tid >> 5, lane = tid & 31;
    const int wm = wid & 1, wn = wid >> 1;
    const int bz = blockIdx.z;
    const size_t rb = (size_t)Kdim * 2;

    const char* gAh = (const char*)(Ah + bz * sA) + (size_t)(blockIdx.y * 128) * rb;
    const char* gAl = (const char*)(Al + bz * sA) + (size_t)(blockIdx.y * 128) * rb;
    const char* gBh = (const char*)(Bh + bz * sB) + (size_t)(blockIdx.x * 128) * rb;
    const char* gBl = (const char*)(Bl + bz * sB) + (size_t)(blockIdx.x * 128) * rb;

    float acc[4][4][4];
    #pragma unroll
    for (int i = 0; i < 4; i++)
        #pragma unroll
        for (int j = 0; j < 4; j++)
            #pragma unroll
            for (int k = 0; k < 4; k++) acc[i][j][k] = 0.f;

    const int NC = Kdim >> 5;

    auto load_stage = [&](int s, int chunk) {
        const uint32_t base = sb + s * 32768;
        const size_t cb = (size_t)chunk * 64;
        #pragma unroll
        for (int j = 0; j < 2; j++) {
            int idx = j * 256 + tid;
            int r = idx >> 2, c = (idx & 3) * 16;
            uint32_t off = SWZ64(r * 64 + c);
            size_t go = (size_t)r * rb + cb + c;
            cp16(base + off,         gAh + go);
            cp16(base + 8192 + off,  gAl + go);
            cp16(base + 16384 + off, gBh + go);
            cp16(base + 24576 + off, gBl + go);
        }
        CP_COMMIT();
    };

    load_stage(0, 0);
    load_stage(1, 1);

    for (int i = 0; i < NC; i++) {
        const int s = i & 1;
        if (i + 1 < NC) { CP_WAIT1(); } else { CP_WAIT0(); }
        __syncthreads();
        const uint32_t aB = sb + s * 32768, bB = aB + 16384;
        #pragma unroll
        for (int ks = 0; ks < 2; ks++) {
            uint32_t ah[4][4], al[4][4], bh[4][2], bl[4][2];
            #pragma unroll
            for (int ma = 0; ma < 4; ma++) {
                int row = wm * 64 + ma * 16 + (lane & 15);
                uint32_t off = SWZ64(row * 64 + ks * 32 + ((lane >> 4) * 16));
                ldsm4(ah[ma], aB + off);
                ldsm4(al[ma], aB + 8192 + off);
            }
            #pragma unroll
            for (int na = 0; na < 4; na++) {
                int row = wn * 32 + na * 8 + (lane & 7);
                uint32_t off = SWZ64(row * 64 + ks * 32 + (((lane >> 3) & 1) * 16));
                ldsm2(bh[na], bB + off);
                ldsm2(bl[na], bB + 8192 + off);
            }
            #pragma unroll
            for (int ma = 0; ma < 4; ma++)
                #pragma unroll
                for (int na = 0; na < 4; na++) {
                    mma16816(acc[ma][na], ah[ma], bh[na]);
                    mma16816(acc[ma][na], ah[ma], bl[na]);
                    mma16816(acc[ma][na], al[ma], bh[na]);
                }
        }
        if (i + 2 < NC) { __syncthreads(); load_stage(s, i + 2); }
    }

    // ---------------- epilogue ----------------
    const int g = lane >> 2, t = lane & 3;
    const int mB = blockIdx.y * 128 + wm * 64;
    const int nB = blockIdx.x * 128 + wn * 32;

    if (EPI == 7) {
        // P = exp(min(acc,80)); stage hi|lo u32 in smem [n_local][m_local],
        // atomic rowsums; then write PT[m][n] coalesced.
        __syncthreads();
        uint32_t* stg = (uint32_t*)smem;   // stride 129
        #pragma unroll
        for (int ma = 0; ma < 4; ma++) {
            const int r0l = wm * 64 + ma * 16 + g;
            const int r1l = r0l + 8;
            float s0 = 0.f, s1 = 0.f;
            #pragma unroll
            for (int na = 0; na < 4; na++) {
                const int c0l = wn * 32 + na * 8 + 2 * t;
                const float* a = acc[ma][na];
                float p0 = __expf(fminf(a[0], 80.f));
                float p1 = __expf(fminf(a[1], 80.f));
                float p2 = __expf(fminf(a[2], 80.f));
                float p3 = __expf(fminf(a[3], 80.f));
                s0 += p0 + p1; s1 += p2 + p3;
                float h0 = __bfloat162float(__float2bfloat16(p0));
                float h1 = __bfloat162float(__float2bfloat16(p1));
                float h2 = __bfloat162float(__float2bfloat16(p2));
                float h3 = __bfloat162float(__float2bfloat16(p3));
                stg[r0l * 129 + c0l]     = pk(h0, p0 - h0);
                stg[r0l * 129 + c0l + 1] = pk(h1, p1 - h1);
                stg[r1l * 129 + c0l]     = pk(h2, p2 - h2);
                stg[r1l * 129 + c0l + 1] = pk(h3, p3 - h3);
            }
            s0 += __shfl_xor_sync(~0u, s0, 1); s0 += __shfl_xor_sync(~0u, s0, 2);
            s1 += __shfl_xor_sync(~0u, s1, 1); s1 += __shfl_xor_sync(~0u, s1, 2);
            if (t == 0) {
                atomicAdd(rsum + (size_t)bz * N_ + blockIdx.y * 128 + r0l, s0);
                atomicAdd(rsum + (size_t)bz * N_ + blockIdx.y * 128 + r1l, s1);
            }
        }
        __syncthreads();
        bf16* PThb = Ch + bz * sC;
        bf16* PTlb = Cl + bz * sC;
        const int rowBase = blockIdx.y * 128;   // n (becomes PT column)
        const int colBase = blockIdx.x * 128;   // m (becomes PT row)
        #pragma unroll
        for (int it = 0; it < 16; it++) {
            const int cloc = wid * 16 + it;
            uint32_t u0 = stg[(lane * 4 + 0) * 129 + cloc];
            uint32_t u1 = stg[(lane * 4 + 1) * 129 + cloc];
            uint32_t u2 = stg[(lane * 4 + 2) * 129 + cloc];
            uint32_t u3 = stg[(lane * 4 + 3) * 129 + cloc];
            uint32_t hp0 = (u0 & 0xFFFFu) | (u1 << 16);
            uint32_t hp1 = (u2 & 0xFFFFu) | (u3 << 16);
            uint32_t lp0 = (u0 >> 16) | (u1 & 0xFFFF0000u);
            uint32_t lp1 = (u2 >> 16) | (u3 & 0xFFFF0000u);
            size_t off = (size_t)(colBase + cloc) * ldC + rowBase + lane * 4;
            *(uint2*)(PThb + off) = make_uint2(hp0, hp1);
            *(uint2*)(PTlb + off) = make_uint2(lp0, lp1);
        }
        return;
    }

    float* Cfb = (EPI <= 2 || EPI == 5) ? Cf + bz * sC : nullptr;
    bf16* Chb = (EPI == 3 || EPI == 4 || EPI == 6) ? Ch + bz * sC : nullptr;
    bf16* Clb = (EPI == 3 || EPI == 4 || EPI == 6) ? Cl + bz * sC : nullptr;
    const float* x2b = (EPI == 5 || EPI == 6) ? x2f + bz * sC : nullptr;

    #pragma unroll
    for (int ma = 0; ma < 4; ma++) {
        const int r0 = mB + ma * 16 + g;
        const int r1 = r0 + 8;
        float p0 = 0.f, p1 = 0.f, iv0 = 0.f, sh0 = 0.f, bo0 = 0.f;
        float iv1 = 0.f, sh1 = 0.f, bo1 = 0.f, cv0 = 0.f, cv1 = 0.f;
        if (EPI == 2 || EPI == 4) { p0 = bias[r0]; p1 = bias[r1]; }
        if (EPI == 5) {
            iv0 = ga[r0] * rsqrtf(rv[r0] + BN_EPS);
            sh0 = be[r0] - rm[r0] * iv0; bo0 = bt[r0];
            iv1 = ga[r1] * rsqrtf(rv[r1] + BN_EPS);
            sh1 = be[r1] - rm[r1] * iv1; bo1 = bt[r1];
        }
        if (EPI == 6) {
            cv0 = 1.f / (1e-9f + bias[(size_t)bz * N_ + r0]);
            cv1 = 1.f / (1e-9f + bias[(size_t)bz * N_ + r1]);
        }
        #pragma unroll
        for (int na = 0; na < 4; na++) {
            const int c0 = nB + na * 8 + 2 * t;
            const float* a = acc[ma][na];
            const size_t o0 = (size_t)r0 * ldC + c0;
            const size_t o1 = (size_t)r1 * ldC + c0;
            if (EPI == 0) {
                *(float2*)(Cfb + o0) = make_float2(a[0], a[1]);
                *(float2*)(Cfb + o1) = make_float2(a[2], a[3]);
            } else if (EPI == 1) {
                float b0 = bias[c0], b1 = bias[c0 + 1];
                *(float2*)(Cfb + o0) = make_float2(a[0] + b0, a[1] + b1);
                *(float2*)(Cfb + o1) = make_float2(a[2] + b0, a[3] + b1);
            } else if (EPI == 2) {
                *(float2*)(Cfb + o0) = make_float2(a[0] + p0, a[1] + p0);
                *(float2*)(Cfb + o1) = make_float2(a[2] + p1, a[3] + p1);
            } else if (EPI == 3 || EPI == 4) {
                float v0 = a[0], v1 = a[1], v2 = a[2], v3 = a[3];
                if (EPI == 4) { v0 += p0; v1 += p0; v2 += p1; v3 += p1; }
                float h0 = __bfloat162float(__float2bfloat16(v0));
                float h1 = __bfloat162float(__float2bfloat16(v1));
                float h2 = __bfloat162float(__float2bfloat16(v2));
                float h3 = __bfloat162float(__float2bfloat16(v3));
                *(uint32_t*)(Chb + o0) = pk(h0, h1);
                *(uint32_t*)(Clb + o0) = pk(v0 - h0, v1 - h1);
                *(uint32_t*)(Chb + o1) = pk(h2, h3);
                *(uint32_t*)(Clb + o1) = pk(v2 - h2, v3 - h3);
            } else if (EPI == 6) {
                float2 x0 = *(const float2*)(x2b + o0);
                float2 x1 = *(const float2*)(x2b + o1);
                float v0 = x0.x - a[0] * cv0, v1 = x0.y - a[1] * cv0;
                float v2 = x1.x - a[2] * cv1, v3 = x1.y - a[3] * cv1;
                float h0 = __bfloat162float(__float2bfloat16(v0));
                float h1 = __bfloat162float(__float2bfloat16(v1));
                float h2 = __bfloat162float(__float2bfloat16(v2));
                float h3 = __bfloat162float(__float2bfloat16(v3));
                *(uint32_t*)(Chb + o0) = pk(h0, h1);
                *(uint32_t*)(Clb + o0) = pk(v0 - h0, v1 - h1);
                *(uint32_t*)(Chb + o1) = pk(h2, h3);
                *(uint32_t*)(Clb + o1) = pk(v2 - h2, v3 - h3);
            } else { // EPI 5
                float2 x0 = *(const float2*)(x2b + o0);
                float2 x1 = *(const float2*)(x2b + o1);
                float2 w0, w1;
                w0.x = fmaxf((a[0] + bo0) * iv0 + sh0, 0.f) + x0.x;
                w0.y = fmaxf((a[1] + bo0) * iv0 + sh0, 0.f) + x0.y;
                w1.x = fmaxf((a[2] + bo1) * iv1 + sh1, 0.f) + x1.x;
                w1.y = fmaxf((a[3] + bo1) * iv1 + sh1, 0.f) + x1.y;
                *(float2*)(Cfb + o0) = w0;
                *(float2*)(Cfb + o1) = w1;
            }
        }
    }
}

// ---------------- aux kernels ----------------------------------------------
__global__ void split_w(const float* __restrict__ w, bf16* __restrict__ h,
                        bf16* __restrict__ l, int n)
{
    int i = blockIdx.x * 256 + threadIdx.x;
    if (i < n) {
        float v = w[i];
        bf16 hv = __float2bfloat16(v);
        h[i] = hv;
        l[i] = __float2bfloat16(v - __bfloat162float(hv));
    }
}

__global__ void tsplit(const float* __restrict__ in, bf16* __restrict__ oh,
                       bf16* __restrict__ ol)
{
    __shared__ float sm[32][33];
    const int b = blockIdx.z;
    const int n0 = blockIdx.x * 32, c0 = blockIdx.y * 32;
    const int r = threadIdx.x >> 5, c = threadIdx.x & 31;
    const float* ip = in + (size_t)b * C2_ * N_;
    #pragma unroll
    for (int k = 0; k < 4; k++)
        sm[r + 8*k][c] = ip[(size_t)(c0 + r + 8*k) * N_ + n0 + c];
    __syncthreads();
    bf16* oph = oh + (size_t)b * N_ * C2_;
    bf16* opl = ol + (size_t)b * N_ * C2_;
    #pragma unroll
    for (int k = 0; k < 4; k++) {
        float v = sm[c][r + 8*k];
        bf16 hv = __float2bfloat16(v);
        size_t o = (size_t)(n0 + r + 8*k) * C2_ + c0 + c;
        oph[o] = hv;
        opl[o] = __float2bfloat16(v - __bfloat162float(hv));
    }
}

__global__ void zero_k(float* p, int n)
{
    int i = blockIdx.x * 256 + threadIdx.x;
    if (i < n) p[i] = 0.f;
}

__global__ void rinvk(const float* __restrict__ rs, float* __restrict__ ri, int n)
{
    int i = blockIdx.x * 256 + threadIdx.x;
    if (i < n) ri[i] = 1.f / rs[i];
}

// V'[b][c][n] = Vf[b][c][n] * rinv[b][n] -> hi/lo split
__global__ void vprime(const float* __restrict__ vf, const float* __restrict__ ri,
                       bf16* __restrict__ vh, bf16* __restrict__ vl)
{
    size_t i = (size_t)blockIdx.x * 256 + threadIdx.x;
    size_t b = i >> 19;                    // C_*N_ = 2^19
    int n = (int)(i & (N_ - 1));
    float v = vf[i] * ri[b * N_ + n];
    bf16 hv = __float2bfloat16(v);
    vh[i] = hv;
    vl[i] = __float2bfloat16(v - __bfloat162float(hv));
}

// cs[row] = sum_n (PTh+PTl)[row][n] * rinv[b][n]   (row = b*N_ + m)
__global__ __launch_bounds__(256)
void colsumk(const bf16* __restrict__ pth, const bf16* __restrict__ ptl,
             const float* __restrict__ ri, float* __restrict__ cs)
{
    const int wid = threadIdx.x >> 5, lane = threadIdx.x & 31;
    const size_t row = (size_t)blockIdx.x * 8 + wid;
    const bf16* ph = pth + row * N_;
    const bf16* pl = ptl + row * N_;
    const float* rv = ri + ((row >> 11) << 11);
    float s = 0.f;
    #pragma unroll
    for (int k = 0; k < 8; k++) {
        int n0 = k * 256 + lane * 8;
        uint4 uh = *(const uint4*)(ph + n0);
        uint4 ul = *(const uint4*)(pl + n0);
        float4 r0 = *(const float4*)(rv + n0);
        float4 r1 = *(const float4*)(rv + n0 + 4);
        const uint32_t* hw = (const uint32_t*)&uh;
        const uint32_t* lw = (const uint32_t*)&ul;
        const float* rr = (const float*)&r0;
        #pragma unroll
        for (int j = 0; j < 4; j++) {
            float2 hv = __bfloat1622float2(*(const __nv_bfloat162*)&hw[j]);
            float2 lv = __bfloat1622float2(*(const __nv_bfloat162*)&lw[j]);
            float ra = (j < 2) ? ((const float*)&r0)[2*j]   : ((const float*)&r1)[2*(j-2)];
            float rb = (j < 2) ? ((const float*)&r0)[2*j+1] : ((const float*)&r1)[2*(j-2)+1];
            s += (hv.x + lv.x) * ra + (hv.y + lv.y) * rb;
        }
        (void)rr;
    }
    #pragma unroll
    for (int o = 16; o > 0; o >>= 1) s += __shfl_xor_sync(~0u, s, o);
    if (lane == 0) cs[row] = s;
}

// ---------------- launcher -------------------------------------------------
extern "C" void kernel_launch(void* const* d_in, const int* in_sizes, int n_in,
                              void* d_out, int out_size)
{
    const float* q  = (const float*)d_in[0];
    const float* x  = (const float*)d_in[1];
    const float* Wq = (const float*)d_in[2];
    const float* Wk = (const float*)d_in[3];
    const float* Wv = (const float*)d_in[4];
    const float* bv = (const float*)d_in[5];
    const float* Wt = (const float*)d_in[6];
    const float* bt = (const float*)d_in[7];
    const float* ga = (const float*)d_in[8];
    const float* be = (const float*)d_in[9];
    const float* rm = (const float*)d_in[10];
    const float* rv = (const float*)d_in[11];
    float* out = (float*)d_out;

    #define SYM(T, p, s) T* p; cudaGetSymbolAddress((void**)&p, s)
    SYM(bf16, qTh, g_qTh); SYM(bf16, qTl, g_qTl);
    SYM(bf16, xTh, g_xTh); SYM(bf16, xTl, g_xTl);
    SYM(bf16, Wqh, g_Wqh); SYM(bf16, Wql, g_Wql);
    SYM(bf16, Wkh, g_Wkh); SYM(bf16, Wkl, g_Wkl);
    SYM(bf16, Wvh, g_Wvh); SYM(bf16, Wvl, g_Wvl);
    SYM(bf16, Wth, g_Wth); SYM(bf16, Wtl, g_Wtl);
    SYM(bf16, QTh, g_QTh); SYM(bf16, QTl, g_QTl);
    SYM(bf16, KTh, g_KTh); SYM(bf16, KTl, g_KTl);
    SYM(float, Vf, g_Vf);
    SYM(bf16, Vph, g_Vph); SYM(bf16, Vpl, g_Vpl);
    SYM(float, X2T, g_X2T); SYM(float, X2f, g_X2f);
    SYM(float, rs, g_rs); SYM(float, ri, g_rinv); SYM(float, cs, g_cs);
    SYM(bf16, PTh, g_PTh); SYM(bf16, PTl, g_PTl);
    SYM(bf16, D2h, g_D2h); SYM(bf16, D2l, g_D2l);
    #undef SYM

    const int SMB  = 65536;
    const int SMB7 = 128 * 129 * 4;   // 66048, epilogue transpose staging
    cudaFuncSetAttribute(mmk<1>, cudaFuncAttributeMaxDynamicSharedMemorySize, SMB);
    cudaFuncSetAttribute(mmk<2>, cudaFuncAttributeMaxDynamicSharedMemorySize, SMB);
    cudaFuncSetAttribute(mmk<3>, cudaFuncAttributeMaxDynamicSharedMemorySize, SMB);
    cudaFuncSetAttribute(mmk<5>, cudaFuncAttributeMaxDynamicSharedMemorySize, SMB);
    cudaFuncSetAttribute(mmk<6>, cudaFuncAttributeMaxDynamicSharedMemorySize, SMB);
    cudaFuncSetAttribute(mmk<7>, cudaFuncAttributeMaxDynamicSharedMemorySize, SMB7);

    const size_t s2 = (size_t)N_ * C2_;
    const size_t sv = (size_t)C_ * N_;
    const size_t sx = (size_t)N_ * C_;
    const size_t se = (size_t)N_ * N_;

    zero_k<<<(B_*N_+255)/256, 256>>>(rs, B_*N_);
    split_w<<<(C2_*C2_+255)/256, 256>>>(Wq, Wqh, Wql, C2_*C2_);
    split_w<<<(C2_*C2_+255)/256, 256>>>(Wk, Wkh, Wkl, C2_*C2_);
    split_w<<<(C_*C2_+255)/256, 256>>>(Wv, Wvh, Wvl, C_*C2_);
    split_w<<<(C_*C_+255)/256, 256>>>(Wt, Wth, Wtl, C_*C_);
    tsplit<<<dim3(N_/32, C2_/32, B_), 256>>>(q, qTh, qTl);
    tsplit<<<dim3(N_/32, C2_/32, B_), 256>>>(x, xTh, xTl);

    // QT[n][o] = qT*Wq^T ; KT[m][o] = xT*Wk^T   (M=2048, Np=128, K=128)
    mmk<3><<<dim3(1,16,B_), 256, SMB>>>(qTh, qTl, Wqh, Wql, nullptr, QTh, QTl,
        C2_, s2, 0, s2, C2_, nullptr, nullptr, nullptr, nullptr, nullptr, nullptr, nullptr, nullptr);
    mmk<3><<<dim3(1,16,B_), 256, SMB>>>(xTh, xTl, Wkh, Wkl, nullptr, KTh, KTl,
        C2_, s2, 0, s2, C2_, nullptr, nullptr, nullptr, nullptr, nullptr, nullptr, nullptr, nullptr);
    // Vf[c][n] = Wv*q + bv[row] (fp32)          (M=256, Np=2048, K=128)
    mmk<2><<<dim3(16,2,B_), 256, SMB>>>(Wvh, Wvl, qTh, qTl, Vf, nullptr, nullptr,
        C2_, 0, s2, sv, N_, bv, nullptr, nullptr, nullptr, nullptr, nullptr, nullptr, nullptr);
    // X2T[n][c] = xT*Wv^T + bv[col]             (M=2048, Np=256, K=128)
    mmk<1><<<dim3(2,16,B_), 256, SMB>>>(xTh, xTl, Wvh, Wvl, X2T, nullptr, nullptr,
        C2_, s2, 0, sx, C_, bv, nullptr, nullptr, nullptr, nullptr, nullptr, nullptr, nullptr);
    // X2f[c][n] = Wv*x + bv[row]                (M=256, Np=2048, K=128)
    mmk<2><<<dim3(16,2,B_), 256, SMB>>>(Wvh, Wvl, xTh, xTl, X2f, nullptr, nullptr,
        C2_, 0, s2, sv, N_, bv, nullptr, nullptr, nullptr, nullptr, nullptr, nullptr, nullptr);
    // E-GEMM -> PT hi/lo + rowsums              (M=2048, Np=2048, K=128)
    mmk<7><<<dim3(16,16,B_), 256, SMB7>>>(QTh, QTl, KTh, KTl, nullptr, PTh, PTl,
        C2_, s2, s2, se, N_, nullptr, nullptr, nullptr, nullptr, nullptr, nullptr, nullptr, rs);
    // rinv, V' = V*rinv, colsum
    rinvk<<<(B_*N_+255)/256, 256>>>(rs, ri, B_*N_);
    vprime<<<(int)((size_t)B_*C_*N_/256), 256>>>(Vf, ri, Vph, Vpl);
    colsumk<<<B_*N_/8, 256>>>(PTh, PTl, ri, cs);
    // XR GEMM -> D2 = split(X2T - acc/cs[row])  (M=2048, Np=256, K=2048)
    mmk<6><<<dim3(2,16,B_), 256, SMB>>>(PTh, PTl, Vph, Vpl, nullptr, D2h, D2l,
        N_, se, sv, sx, C_, cs, X2T, nullptr, nullptr, nullptr, nullptr, nullptr, nullptr);
    // out[c][n] = relu(bn(Wt*D2 + bt)) + X2f    (M=256, Np=2048, K=256)
    mmk<5><<<dim3(16,2,B_), 256, SMB>>>(Wth, Wtl, D2h, D2l, out, nullptr, nullptr,
        C_, 0, sx, sv, N_, nullptr, X2f, ga, be, rm, rv, bt, nullptr);
}

// round 11
// speedup vs baseline: 2.4169x; 1.2455x over previous
#include <cuda_runtime.h>
#include <cuda_bf16.h>
#include <cuda_fp16.h>
#include <cstdint>

#define B_  16
#define C_  256
#define C2_ 128
#define N_  2048
#define BN_EPS 1e-5f
typedef __nv_bfloat16 bf16;

// ---------------- scratch (device globals) ---------------------------------
__device__ __align__(128) bf16 g_qTh[(size_t)B_*N_*C2_], g_qTl[(size_t)B_*N_*C2_];
__device__ __align__(128) bf16 g_xTh[(size_t)B_*N_*C2_], g_xTl[(size_t)B_*N_*C2_];
__device__ __align__(128) bf16 g_Wqh[C2_*C2_], g_Wql[C2_*C2_];
__device__ __align__(128) bf16 g_Wkh[C2_*C2_], g_Wkl[C2_*C2_];
__device__ __align__(128) bf16 g_Wvh[C_*C2_],  g_Wvl[C_*C2_];
__device__ __align__(128) bf16 g_Wth[C_*C_],   g_Wtl[C_*C_];
__device__ __align__(128) bf16 g_QTh[(size_t)B_*N_*C2_], g_QTl[(size_t)B_*N_*C2_];
__device__ __align__(128) bf16 g_KTh[(size_t)B_*N_*C2_], g_KTl[(size_t)B_*N_*C2_];
__device__ __align__(128) __half g_V16[(size_t)B_*C_*N_];
__device__ __align__(128) float g_X2T[(size_t)B_*N_*C_];
__device__ __align__(128) float g_X2f[(size_t)B_*C_*N_];
__device__ __align__(128) float g_rs[(size_t)B_*N_], g_rinv[(size_t)B_*N_];
__device__ __align__(128) bf16 g_PTh[(size_t)B_*N_*N_], g_PTl[(size_t)B_*N_*N_];
__device__ __align__(128) __half g_S16[(size_t)B_*N_*N_];
__device__ __align__(128) bf16 g_D2h[(size_t)B_*N_*C_], g_D2l[(size_t)B_*N_*C_];

// ---------------- helpers --------------------------------------------------
__device__ __forceinline__ uint32_t smem_u32(const void* p) {
    uint32_t a;
    asm("{ .reg .u64 t; cvta.to.shared.u64 t, %1; cvt.u32.u64 %0, t; }" : "=r"(a) : "l"(p));
    return a;
}
#define SWZ64(x) ((x) ^ (((x) >> 3) & 0x30))
#define CP_COMMIT() asm volatile("cp.async.commit_group;" ::: "memory")
#define CP_WAIT1()  asm volatile("cp.async.wait_group 1;" ::: "memory")
#define CP_WAIT0()  asm volatile("cp.async.wait_group 0;" ::: "memory")

__device__ __forceinline__ void cp16(uint32_t dst, const void* src) {
    asm volatile("cp.async.cg.shared.global [%0], [%1], 16;" :: "r"(dst), "l"(src));
}
__device__ __forceinline__ void ldsm4(uint32_t* r, uint32_t a) {
    asm volatile("ldmatrix.sync.aligned.m8n8.x4.shared.b16 {%0,%1,%2,%3}, [%4];"
        : "=r"(r[0]), "=r"(r[1]), "=r"(r[2]), "=r"(r[3]) : "r"(a));
}
__device__ __forceinline__ void ldsm2(uint32_t* r, uint32_t a) {
    asm volatile("ldmatrix.sync.aligned.m8n8.x2.shared.b16 {%0,%1}, [%2];"
        : "=r"(r[0]), "=r"(r[1]) : "r"(a));
}
template<int HALF>
__device__ __forceinline__ void mma16816(float* d, const uint32_t* a, const uint32_t* b) {
    if (HALF)
        asm volatile("mma.sync.aligned.m16n8k16.row.col.f32.f16.f16.f32 "
            "{%0,%1,%2,%3}, {%4,%5,%6,%7}, {%8,%9}, {%0,%1,%2,%3};"
            : "+f"(d[0]), "+f"(d[1]), "+f"(d[2]), "+f"(d[3])
            : "r"(a[0]), "r"(a[1]), "r"(a[2]), "r"(a[3]), "r"(b[0]), "r"(b[1]));
    else
        asm volatile("mma.sync.aligned.m16n8k16.row.col.f32.bf16.bf16.f32 "
            "{%0,%1,%2,%3}, {%4,%5,%6,%7}, {%8,%9}, {%0,%1,%2,%3};"
            : "+f"(d[0]), "+f"(d[1]), "+f"(d[2]), "+f"(d[3])
            : "r"(a[0]), "r"(a[1]), "r"(a[2]), "r"(a[3]), "r"(b[0]), "r"(b[1]));
}
__device__ __forceinline__ uint32_t pk(float a, float b) {
    __nv_bfloat162 t = __floats2bfloat162_rn(a, b);
    return *reinterpret_cast<uint32_t*>(&t);
}

// ---------------- warp-MMA GEMM --------------------------------------------
// C[M, Np] = A[M,K] * B[Np,K]^T, K-major 16-bit operands.
// SPLIT=1: A,B given as hi/lo pairs, 3-term split product. SPLIT=0: single.
// Tile 128x128, Kc=32, double-buffered cp.async, 8 warps of 64x32.
// EPI: 1 f32+bias[col] | 2 f32+bias[row] | 3 split hi/lo | 5 final relu(bn)+x2
//      6 XR: split(x2t - acc) | 7 E: exp + transposed hi/lo + rowsums
//      8 fp16 out + bias[row]
template<int EPI, int SPLIT, int HALF>
__global__ __launch_bounds__(256, 1)
void mmk(const bf16* __restrict__ Ah, const bf16* __restrict__ Al,
         const bf16* __restrict__ Bh, const bf16* __restrict__ Bl,
         float* __restrict__ Cf, bf16* __restrict__ Ch, bf16* __restrict__ Cl,
         int Kdim, size_t sA, size_t sB, size_t sC, int ldC,
         const float* __restrict__ bias, const float* __restrict__ x2f,
         const float* __restrict__ ga, const float* __restrict__ be,
         const float* __restrict__ rm, const float* __restrict__ rv,
         const float* __restrict__ bt, float* __restrict__ rsum)
{
    constexpr int STG  = SPLIT ? 32768 : 16384;
    constexpr int BOFF = SPLIT ? 16384 : 8192;

    extern __shared__ __align__(128) char smem[];
    const uint32_t sb = smem_u32(smem);
    const int tid = threadIdx.x, wid = tid >> 5, lane = tid & 31;
    const int wm = wid & 1, wn = wid >> 1;
    const int bz = blockIdx.z;
    const size_t rb = (size_t)Kdim * 2;

    const char* gAh = (const char*)(Ah + bz * sA) + (size_t)(blockIdx.y * 128) * rb;
    const char* gAl = SPLIT ? (const char*)(Al + bz * sA) + (size_t)(blockIdx.y * 128) * rb : nullptr;
    const char* gBh = (const char*)(Bh + bz * sB) + (size_t)(blockIdx.x * 128) * rb;
    const char* gBl = SPLIT ? (const char*)(Bl + bz * sB) + (size_t)(blockIdx.x * 128) * rb : nullptr;

    float acc[4][4][4];
    #pragma unroll
    for (int i = 0; i < 4; i++)
        #pragma unroll
        for (int j = 0; j < 4; j++)
            #pragma unroll
            for (int k = 0; k < 4; k++) acc[i][j][k] = 0.f;

    const int NC = Kdim >> 5;

    auto load_stage = [&](int s, int chunk) {
        const uint32_t base = sb + s * STG;
        const size_t cb = (size_t)chunk * 64;
        #pragma unroll
        for (int j = 0; j < 2; j++) {
            int idx = j * 256 + tid;
            int r = idx >> 2, c = (idx & 3) * 16;
            uint32_t off = SWZ64(r * 64 + c);
            size_t go = (size_t)r * rb + cb + c;
            cp16(base + off,        gAh + go);
            cp16(base + BOFF + off, gBh + go);
            if (SPLIT) {
                cp16(base + 8192 + off,  gAl + go);
                cp16(base + 24576 + off, gBl + go);
            }
        }
        CP_COMMIT();
    };

    load_stage(0, 0);
    load_stage(1, 1);

    for (int i = 0; i < NC; i++) {
        const int s = i & 1;
        if (i + 1 < NC) { CP_WAIT1(); } else { CP_WAIT0(); }
        __syncthreads();
        const uint32_t aB = sb + s * STG, bB = aB + BOFF;
        #pragma unroll
        for (int ks = 0; ks < 2; ks++) {
            uint32_t ah[4][4], al[4][4], bh[4][2], bl[4][2];
            #pragma unroll
            for (int ma = 0; ma < 4; ma++) {
                int row = wm * 64 + ma * 16 + (lane & 15);
                uint32_t off = SWZ64(row * 64 + ks * 32 + ((lane >> 4) * 16));
                ldsm4(ah[ma], aB + off);
                if (SPLIT) ldsm4(al[ma], aB + 8192 + off);
            }
            #pragma unroll
            for (int na = 0; na < 4; na++) {
                int row = wn * 32 + na * 8 + (lane & 7);
                uint32_t off = SWZ64(row * 64 + ks * 32 + (((lane >> 3) & 1) * 16));
                ldsm2(bh[na], bB + off);
                if (SPLIT) ldsm2(bl[na], bB + 8192 + off);
            }
            #pragma unroll
            for (int ma = 0; ma < 4; ma++)
                #pragma unroll
                for (int na = 0; na < 4; na++) {
                    mma16816<HALF>(acc[ma][na], ah[ma], bh[na]);
                    if (SPLIT) {
                        mma16816<HALF>(acc[ma][na], ah[ma], bl[na]);
                        mma16816<HALF>(acc[ma][na], al[ma], bh[na]);
                    }
                }
        }
        if (i + 2 < NC) { __syncthreads(); load_stage(s, i + 2); }
    }

    // ---------------- epilogue ----------------
    const int g = lane >> 2, t = lane & 3;
    const int mB = blockIdx.y * 128 + wm * 64;
    const int nB = blockIdx.x * 128 + wn * 32;

    if (EPI == 7) {
        __syncthreads();
        uint32_t* stg = (uint32_t*)smem;   // stride 129
        #pragma unroll
        for (int ma = 0; ma < 4; ma++) {
            const int r0l = wm * 64 + ma * 16 + g;
            const int r1l = r0l + 8;
            float s0 = 0.f, s1 = 0.f;
            #pragma unroll
            for (int na = 0; na < 4; na++) {
                const int c0l = wn * 32 + na * 8 + 2 * t;
                const float* a = acc[ma][na];
                float p0 = __expf(fminf(a[0], 80.f));
                float p1 = __expf(fminf(a[1], 80.f));
                float p2 = __expf(fminf(a[2], 80.f));
                float p3 = __expf(fminf(a[3], 80.f));
                s0 += p0 + p1; s1 += p2 + p3;
                float h0 = __bfloat162float(__float2bfloat16(p0));
                float h1 = __bfloat162float(__float2bfloat16(p1));
                float h2 = __bfloat162float(__float2bfloat16(p2));
                float h3 = __bfloat162float(__float2bfloat16(p3));
                stg[r0l * 129 + c0l]     = pk(h0, p0 - h0);
                stg[r0l * 129 + c0l + 1] = pk(h1, p1 - h1);
                stg[r1l * 129 + c0l]     = pk(h2, p2 - h2);
                stg[r1l * 129 + c0l + 1] = pk(h3, p3 - h3);
            }
            s0 += __shfl_xor_sync(~0u, s0, 1); s0 += __shfl_xor_sync(~0u, s0, 2);
            s1 += __shfl_xor_sync(~0u, s1, 1); s1 += __shfl_xor_sync(~0u, s1, 2);
            if (t == 0) {
                atomicAdd(rsum + (size_t)bz * N_ + blockIdx.y * 128 + r0l, s0);
                atomicAdd(rsum + (size_t)bz * N_ + blockIdx.y * 128 + r1l, s1);
            }
        }
        __syncthreads();
        bf16* PThb = Ch + bz * sC;
        bf16* PTlb = Cl + bz * sC;
        const int rowBase = blockIdx.y * 128;
        const int colBase = blockIdx.x * 128;
        #pragma unroll
        for (int it = 0; it < 16; it++) {
            const int cloc = wid * 16 + it;
            uint32_t u0 = stg[(lane * 4 + 0) * 129 + cloc];
            uint32_t u1 = stg[(lane * 4 + 1) * 129 + cloc];
            uint32_t u2 = stg[(lane * 4 + 2) * 129 + cloc];
            uint32_t u3 = stg[(lane * 4 + 3) * 129 + cloc];
            uint32_t hp0 = (u0 & 0xFFFFu) | (u1 << 16);
            uint32_t hp1 = (u2 & 0xFFFFu) | (u3 << 16);
            uint32_t lp0 = (u0 >> 16) | (u1 & 0xFFFF0000u);
            uint32_t lp1 = (u2 >> 16) | (u3 & 0xFFFF0000u);
            size_t off = (size_t)(colBase + cloc) * ldC + rowBase + lane * 4;
            *(uint2*)(PThb + off) = make_uint2(hp0, hp1);
            *(uint2*)(PTlb + off) = make_uint2(lp0, lp1);
        }
        return;
    }

    float* Cfb = (EPI <= 2 || EPI == 5) ? Cf + bz * sC : nullptr;
    bf16* Chb = (EPI == 3 || EPI == 6 || EPI == 8) ? Ch + bz * sC : nullptr;
    bf16* Clb = (EPI == 3 || EPI == 6) ? Cl + bz * sC : nullptr;
    const float* x2b = (EPI == 5 || EPI == 6) ? x2f + bz * sC : nullptr;

    #pragma unroll
    for (int ma = 0; ma < 4; ma++) {
        const int r0 = mB + ma * 16 + g;
        const int r1 = r0 + 8;
        float p0 = 0.f, p1 = 0.f, iv0 = 0.f, sh0 = 0.f, bo0 = 0.f;
        float iv1 = 0.f, sh1 = 0.f, bo1 = 0.f;
        if (EPI == 2 || EPI == 8) { p0 = bias[r0]; p1 = bias[r1]; }
        if (EPI == 5) {
            iv0 = ga[r0] * rsqrtf(rv[r0] + BN_EPS);
            sh0 = be[r0] - rm[r0] * iv0; bo0 = bt[r0];
            iv1 = ga[r1] * rsqrtf(rv[r1] + BN_EPS);
            sh1 = be[r1] - rm[r1] * iv1; bo1 = bt[r1];
        }
        #pragma unroll
        for (int na = 0; na < 4; na++) {
            const int c0 = nB + na * 8 + 2 * t;
            const float* a = acc[ma][na];
            const size_t o0 = (size_t)r0 * ldC + c0;
            const size_t o1 = (size_t)r1 * ldC + c0;
            if (EPI == 1) {
                float b0 = bias[c0], b1 = bias[c0 + 1];
                *(float2*)(Cfb + o0) = make_float2(a[0] + b0, a[1] + b1);
                *(float2*)(Cfb + o1) = make_float2(a[2] + b0, a[3] + b1);
            } else if (EPI == 2) {
                *(float2*)(Cfb + o0) = make_float2(a[0] + p0, a[1] + p0);
                *(float2*)(Cfb + o1) = make_float2(a[2] + p1, a[3] + p1);
            } else if (EPI == 3) {
                float v0 = a[0], v1 = a[1], v2 = a[2], v3 = a[3];
                float h0 = __bfloat162float(__float2bfloat16(v0));
                float h1 = __bfloat162float(__float2bfloat16(v1));
                float h2 = __bfloat162float(__float2bfloat16(v2));
                float h3 = __bfloat162float(__float2bfloat16(v3));
                *(uint32_t*)(Chb + o0) = pk(h0, h1);
                *(uint32_t*)(Clb + o0) = pk(v0 - h0, v1 - h1);
                *(uint32_t*)(Chb + o1) = pk(h2, h3);
                *(uint32_t*)(Clb + o1) = pk(v2 - h2, v3 - h3);
            } else if (EPI == 6) {
                float2 x0 = *(const float2*)(x2b + o0);
                float2 x1 = *(const float2*)(x2b + o1);
                float v0 = x0.x - a[0], v1 = x0.y - a[1];
                float v2 = x1.x - a[2], v3 = x1.y - a[3];
                float h0 = __bfloat162float(__float2bfloat16(v0));
                float h1 = __bfloat162float(__float2bfloat16(v1));
                float h2 = __bfloat162float(__float2bfloat16(v2));
                float h3 = __bfloat162float(__float2bfloat16(v3));
                *(uint32_t*)(Chb + o0) = pk(h0, h1);
                *(uint32_t*)(Clb + o0) = pk(v0 - h0, v1 - h1);
                *(uint32_t*)(Chb + o1) = pk(h2, h3);
                *(uint32_t*)(Clb + o1) = pk(v2 - h2, v3 - h3);
            } else if (EPI == 8) {
                __half2 a0 = __floats2half2_rn(a[0] + p0, a[1] + p0);
                __half2 a1 = __floats2half2_rn(a[2] + p1, a[3] + p1);
                *(__half2*)((__half*)Chb + o0) = a0;
                *(__half2*)((__half*)Chb + o1) = a1;
            } else { // EPI 5
                float2 x0 = *(const float2*)(x2b + o0);
                float2 x1 = *(const float2*)(x2b + o1);
                float2 w0, w1;
                w0.x = fmaxf((a[0] + bo0) * iv0 + sh0, 0.f) + x0.x;
                w0.y = fmaxf((a[1] + bo0) * iv0 + sh0, 0.f) + x0.y;
                w1.x = fmaxf((a[2] + bo1) * iv1 + sh1, 0.f) + x1.x;
                w1.y = fmaxf((a[3] + bo1) * iv1 + sh1, 0.f) + x1.y;
                *(float2*)(Cfb + o0) = w0;
                *(float2*)(Cfb + o1) = w1;
            }
        }
    }
}

// ---------------- aux kernels ----------------------------------------------
__global__ void split_w(const float* __restrict__ w, bf16* __restrict__ h,
                        bf16* __restrict__ l, int n)
{
    int i = blockIdx.x * 256 + threadIdx.x;
    if (i < n) {
        float v = w[i];
        bf16 hv = __float2bfloat16(v);
        h[i] = hv;
        l[i] = __float2bfloat16(v - __bfloat162float(hv));
    }
}

__global__ void tsplit(const float* __restrict__ in, bf16* __restrict__ oh,
                       bf16* __restrict__ ol)
{
    __shared__ float sm[32][33];
    const int b = blockIdx.z;
    const int n0 = blockIdx.x * 32, c0 = blockIdx.y * 32;
    const int r = threadIdx.x >> 5, c = threadIdx.x & 31;
    const float* ip = in + (size_t)b * C2_ * N_;
    #pragma unroll
    for (int k = 0; k < 4; k++)
        sm[r + 8*k][c] = ip[(size_t)(c0 + r + 8*k) * N_ + n0 + c];
    __syncthreads();
    bf16* oph = oh + (size_t)b * N_ * C2_;
    bf16* opl = ol + (size_t)b * N_ * C2_;
    #pragma unroll
    for (int k = 0; k < 4; k++) {
        float v = sm[c][r + 8*k];
        bf16 hv = __float2bfloat16(v);
        size_t o = (size_t)(n0 + r + 8*k) * C2_ + c0 + c;
        oph[o] = hv;
        opl[o] = __float2bfloat16(v - __bfloat162float(hv));
    }
}

__global__ void zero_k(float* p, int n)
{
    int i = blockIdx.x * 256 + threadIdx.x;
    if (i < n) p[i] = 0.f;
}

__global__ void rinvk(const float* __restrict__ rs, float* __restrict__ ri, int n)
{
    int i = blockIdx.x * 256 + threadIdx.x;
    if (i < n) ri[i] = 1.f / rs[i];
}

// Per PT row m: cs = sum_n (Ph+Pl)*rinv[n]; S16[m][n] = (Ph+Pl)*rinv[n]/(1e-9+cs)
__global__ __launch_bounds__(256)
void normk(const bf16* __restrict__ pth, const bf16* __restrict__ ptl,
           const float* __restrict__ ri, __half* __restrict__ s16)
{
    const int wid = threadIdx.x >> 5, lane = threadIdx.x & 31;
    const size_t row = (size_t)blockIdx.x * 8 + wid;
    const bf16* ph = pth + row * N_;
    const bf16* pl = ptl + row * N_;
    const float* rv = ri + ((row >> 11) << 11);
    float v[64];
    float s = 0.f;
    #pragma unroll
    for (int k = 0; k < 8; k++) {
        int n0 = k * 256 + lane * 8;
        uint4 uh = *(const uint4*)(ph + n0);
        uint4 ul = *(const uint4*)(pl + n0);
        float4 r0 = *(const float4*)(rv + n0);
        float4 r1 = *(const float4*)(rv + n0 + 4);
        float rr[8];
        *(float4*)rr = r0; *(float4*)(rr + 4) = r1;
        const uint32_t* hw = (const uint32_t*)&uh;
        const uint32_t* lw = (const uint32_t*)&ul;
        #pragma unroll
        for (int j = 0; j < 4; j++) {
            float2 hv = __bfloat1622float2(*(const __nv_bfloat162*)&hw[j]);
            float2 lv = __bfloat1622float2(*(const __nv_bfloat162*)&lw[j]);
            float a = (hv.x + lv.x) * rr[2*j];
            float b = (hv.y + lv.y) * rr[2*j + 1];
            v[k*8 + 2*j] = a; v[k*8 + 2*j + 1] = b;
            s += a + b;
        }
    }
    #pragma unroll
    for (int o = 16; o > 0; o >>= 1) s += __shfl_xor_sync(~0u, s, o);
    const float inv = 1.f / (1e-9f + s);
    __half* op = s16 + row * N_;
    #pragma unroll
    for (int k = 0; k < 8; k++) {
        int n0 = k * 256 + lane * 8;
        __half2 h4[4];
        #pragma unroll
        for (int j = 0; j < 4; j++)
            h4[j] = __floats2half2_rn(v[k*8 + 2*j] * inv, v[k*8 + 2*j + 1] * inv);
        *(uint4*)(op + n0) = *(uint4*)h4;
    }
}

// ---------------- launcher -------------------------------------------------
extern "C" void kernel_launch(void* const* d_in, const int* in_sizes, int n_in,
                              void* d_out, int out_size)
{
    const float* q  = (const float*)d_in[0];
    const float* x  = (const float*)d_in[1];
    const float* Wq = (const float*)d_in[2];
    const float* Wk = (const float*)d_in[3];
    const float* Wv = (const float*)d_in[4];
    const float* bv = (const float*)d_in[5];
    const float* Wt = (const float*)d_in[6];
    const float* bt = (const float*)d_in[7];
    const float* ga = (const float*)d_in[8];
    const float* be = (const float*)d_in[9];
    const float* rm = (const float*)d_in[10];
    const float* rv = (const float*)d_in[11];
    float* out = (float*)d_out;

    #define SYM(T, p, s) T* p; cudaGetSymbolAddress((void**)&p, s)
    SYM(bf16, qTh, g_qTh); SYM(bf16, qTl, g_qTl);
    SYM(bf16, xTh, g_xTh); SYM(bf16, xTl, g_xTl);
    SYM(bf16, Wqh, g_Wqh); SYM(bf16, Wql, g_Wql);
    SYM(bf16, Wkh, g_Wkh); SYM(bf16, Wkl, g_Wkl);
    SYM(bf16, Wvh, g_Wvh); SYM(bf16, Wvl, g_Wvl);
    SYM(bf16, Wth, g_Wth); SYM(bf16, Wtl, g_Wtl);
    SYM(bf16, QTh, g_QTh); SYM(bf16, QTl, g_QTl);
    SYM(bf16, KTh, g_KTh); SYM(bf16, KTl, g_KTl);
    SYM(__half, V16, g_V16);
    SYM(float, X2T, g_X2T); SYM(float, X2f, g_X2f);
    SYM(float, rs, g_rs); SYM(float, ri, g_rinv);
    SYM(bf16, PTh, g_PTh); SYM(bf16, PTl, g_PTl);
    SYM(__half, S16, g_S16);
    SYM(bf16, D2h, g_D2h); SYM(bf16, D2l, g_D2l);
    #undef SYM

    const int SMB  = 65536;
    const int SMB7 = 128 * 129 * 4;
    const int SMB1 = 32768;
    cudaFuncSetAttribute(mmk<1,1,0>, cudaFuncAttributeMaxDynamicSharedMemorySize, SMB);
    cudaFuncSetAttribute(mmk<2,1,0>, cudaFuncAttributeMaxDynamicSharedMemorySize, SMB);
    cudaFuncSetAttribute(mmk<3,1,0>, cudaFuncAttributeMaxDynamicSharedMemorySize, SMB);
    cudaFuncSetAttribute(mmk<5,1,0>, cudaFuncAttributeMaxDynamicSharedMemorySize, SMB);
    cudaFuncSetAttribute(mmk<7,1,0>, cudaFuncAttributeMaxDynamicSharedMemorySize, SMB7);
    cudaFuncSetAttribute(mmk<8,1,0>, cudaFuncAttributeMaxDynamicSharedMemorySize, SMB);
    cudaFuncSetAttribute(mmk<6,0,1>, cudaFuncAttributeMaxDynamicSharedMemorySize, SMB1);

    const size_t s2 = (size_t)N_ * C2_;
    const size_t sv = (size_t)C_ * N_;
    const size_t sx = (size_t)N_ * C_;
    const size_t se = (size_t)N_ * N_;

    zero_k<<<(B_*N_+255)/256, 256>>>(rs, B_*N_);
    split_w<<<(C2_*C2_+255)/256, 256>>>(Wq, Wqh, Wql, C2_*C2_);
    split_w<<<(C2_*C2_+255)/256, 256>>>(Wk, Wkh, Wkl, C2_*C2_);
    split_w<<<(C_*C2_+255)/256, 256>>>(Wv, Wvh, Wvl, C_*C2_);
    split_w<<<(C_*C_+255)/256, 256>>>(Wt, Wth, Wtl, C_*C_);
    tsplit<<<dim3(N_/32, C2_/32, B_), 256>>>(q, qTh, qTl);
    tsplit<<<dim3(N_/32, C2_/32, B_), 256>>>(x, xTh, xTl);

    // QT[n][o] = qT*Wq^T ; KT[m][o] = xT*Wk^T   (M=2048, Np=128, K=128)
    mmk<3,1,0><<<dim3(1,16,B_), 256, SMB>>>(qTh, qTl, Wqh, Wql, nullptr, QTh, QTl,
        C2_, s2, 0, s2, C2_, nullptr, nullptr, nullptr, nullptr, nullptr, nullptr, nullptr, nullptr);
    mmk<3,1,0><<<dim3(1,16,B_), 256, SMB>>>(xTh, xTl, Wkh, Wkl, nullptr, KTh, KTl,
        C2_, s2, 0, s2, C2_, nullptr, nullptr, nullptr, nullptr, nullptr, nullptr, nullptr, nullptr);
    // V16[c][n] = fp16(Wv*q + bv[row])          (M=256, Np=2048, K=128)
    mmk<8,1,0><<<dim3(16,2,B_), 256, SMB>>>(Wvh, Wvl, qTh, qTl, nullptr, (bf16*)V16, nullptr,
        C2_, 0, s2, sv, N_, bv, nullptr, nullptr, nullptr, nullptr, nullptr, nullptr, nullptr);
    // X2T[n][c] = xT*Wv^T + bv[col]             (M=2048, Np=256, K=128)
    mmk<1,1,0><<<dim3(2,16,B_), 256, SMB>>>(xTh, xTl, Wvh, Wvl, X2T, nullptr, nullptr,
        C2_, s2, 0, sx, C_, bv, nullptr, nullptr, nullptr, nullptr, nullptr, nullptr, nullptr);
    // X2f[c][n] = Wv*x + bv[row]                (M=256, Np=2048, K=128)
    mmk<2,1,0><<<dim3(16,2,B_), 256, SMB>>>(Wvh, Wvl, xTh, xTl, X2f, nullptr, nullptr,
        C2_, 0, s2, sv, N_, bv, nullptr, nullptr, nullptr, nullptr, nullptr, nullptr, nullptr);
    // E-GEMM -> PT hi/lo + rowsums              (M=2048, Np=2048, K=128)
    mmk<7,1,0><<<dim3(16,16,B_), 256, SMB7>>>(QTh, QTl, KTh, KTl, nullptr, PTh, PTl,
        C2_, s2, s2, se, N_, nullptr, nullptr, nullptr, nullptr, nullptr, nullptr, nullptr, rs);
    // rinv; fully-normalized S16 (fp16)
    rinvk<<<(B_*N_+255)/256, 256>>>(rs, ri, B_*N_);
    normk<<<B_*N_/8, 256>>>(PTh, PTl, ri, S16);
    // XR GEMM (single fp16) -> D2 = split(X2T - acc)   (M=2048, Np=256, K=2048)
    mmk<6,0,1><<<dim3(2,16,B_), 256, SMB1>>>((const bf16*)S16, nullptr, (const bf16*)V16, nullptr,
        nullptr, D2h, D2l, N_, se, sv, sx, C_, nullptr, X2T, nullptr, nullptr, nullptr, nullptr, nullptr, nullptr);
    // out[c][n] = relu(bn(Wt*D2 + bt)) + X2f    (M=256, Np=2048, K=256)
    mmk<5,1,0><<<dim3(16,2,B_), 256, SMB>>>(Wth, Wtl, D2h, D2l, out, nullptr, nullptr,
        C_, 0, sx, sv, N_, nullptr, X2f, ga, be, rm, rv, bt, nullptr);
}

// round 13
// speedup vs baseline: 2.5615x; 1.0599x over previous
#include <cuda_runtime.h>
#include <cuda_bf16.h>
#include <cuda_fp16.h>
#include <cstdint>

#define B_  16
#define C_  256
#define C2_ 128
#define N_  2048
#define BN_EPS 1e-5f
typedef __nv_bfloat16 bf16;

// ---------------- scratch (device globals) ---------------------------------
__device__ __align__(128) bf16 g_qTh[(size_t)B_*N_*C2_], g_qTl[(size_t)B_*N_*C2_];
__device__ __align__(128) bf16 g_xTh[(size_t)B_*N_*C2_], g_xTl[(size_t)B_*N_*C2_];
__device__ __align__(128) bf16 g_Wqh[C2_*C2_], g_Wql[C2_*C2_];
__device__ __align__(128) bf16 g_Wkh[C2_*C2_], g_Wkl[C2_*C2_];
__device__ __align__(128) bf16 g_Wvh[C_*C2_],  g_Wvl[C_*C2_];
__device__ __align__(128) bf16 g_Wth[C_*C_],   g_Wtl[C_*C_];
__device__ __align__(128) bf16 g_QTh[(size_t)B_*N_*C2_], g_QTl[(size_t)B_*N_*C2_];
__device__ __align__(128) bf16 g_KTh[(size_t)B_*N_*C2_], g_KTl[(size_t)B_*N_*C2_];
__device__ __align__(128) __half g_V16[(size_t)B_*C_*N_];
__device__ __align__(128) float g_X2T[(size_t)B_*N_*C_];
__device__ __align__(128) float g_X2f[(size_t)B_*C_*N_];
__device__ __align__(128) float g_rs[(size_t)B_*N_], g_rinv[(size_t)B_*N_];
__device__ __align__(128) bf16 g_PTh[(size_t)B_*N_*N_], g_PTl[(size_t)B_*N_*N_];
__device__ __align__(128) __half g_S16[(size_t)B_*N_*N_];
__device__ __align__(128) bf16 g_D2h[(size_t)B_*N_*C_], g_D2l[(size_t)B_*N_*C_];

// ---------------- helpers --------------------------------------------------
__device__ __forceinline__ uint32_t smem_u32(const void* p) {
    uint32_t a;
    asm("{ .reg .u64 t; cvta.to.shared.u64 t, %1; cvt.u32.u64 %0, t; }" : "=r"(a) : "l"(p));
    return a;
}
#define SWZ64(x) ((x) ^ (((x) >> 3) & 0x30))
#define CP_COMMIT() asm volatile("cp.async.commit_group;" ::: "memory")
#define CP_WAIT1()  asm volatile("cp.async.wait_group 1;" ::: "memory")
#define CP_WAIT0()  asm volatile("cp.async.wait_group 0;" ::: "memory")

__device__ __forceinline__ void cp16(uint32_t dst, const void* src) {
    asm volatile("cp.async.cg.shared.global [%0], [%1], 16;" :: "r"(dst), "l"(src));
}
__device__ __forceinline__ void ldsm4(uint32_t* r, uint32_t a) {
    asm volatile("ldmatrix.sync.aligned.m8n8.x4.shared.b16 {%0,%1,%2,%3}, [%4];"
        : "=r"(r[0]), "=r"(r[1]), "=r"(r[2]), "=r"(r[3]) : "r"(a));
}
__device__ __forceinline__ void ldsm2(uint32_t* r, uint32_t a) {
    asm volatile("ldmatrix.sync.aligned.m8n8.x2.shared.b16 {%0,%1}, [%2];"
        : "=r"(r[0]), "=r"(r[1]) : "r"(a));
}
template<int HALF>
__device__ __forceinline__ void mma16816(float* d, const uint32_t* a, const uint32_t* b) {
    if (HALF)
        asm volatile("mma.sync.aligned.m16n8k16.row.col.f32.f16.f16.f32 "
            "{%0,%1,%2,%3}, {%4,%5,%6,%7}, {%8,%9}, {%0,%1,%2,%3};"
            : "+f"(d[0]), "+f"(d[1]), "+f"(d[2]), "+f"(d[3])
            : "r"(a[0]), "r"(a[1]), "r"(a[2]), "r"(a[3]), "r"(b[0]), "r"(b[1]));
    else
        asm volatile("mma.sync.aligned.m16n8k16.row.col.f32.bf16.bf16.f32 "
            "{%0,%1,%2,%3}, {%4,%5,%6,%7}, {%8,%9}, {%0,%1,%2,%3};"
            : "+f"(d[0]), "+f"(d[1]), "+f"(d[2]), "+f"(d[3])
            : "r"(a[0]), "r"(a[1]), "r"(a[2]), "r"(a[3]), "r"(b[0]), "r"(b[1]));
}
__device__ __forceinline__ uint32_t pk(float a, float b) {
    __nv_bfloat162 t = __floats2bfloat162_rn(a, b);
    return *reinterpret_cast<uint32_t*>(&t);
}

// ---------------- warp-MMA GEMM --------------------------------------------
// C[M, Np] = A[M,K] * B[Np,K]^T, K-major 16-bit operands.
// SPLIT=1: hi/lo pairs, 3-term split product. Tile 128x128, Kc=32,
// 3-buffer cp.async pipeline (single sync/iter), 8 warps of 64x32.
// EPI: 1 f32+bias[col] | 5 final relu(bn)+x2 | 6 XR: split(x2t - acc)
//      7 E: exp + transposed hi/lo + rowsums | 9 merged V16(fp16)/X2f(f32)
//      10 merged QK split-out
template<int EPI, int SPLIT, int HALF>
__global__ __launch_bounds__(256, 1)
void mmk(const bf16* __restrict__ Ah, const bf16* __restrict__ Al,
         const bf16* __restrict__ Bh, const bf16* __restrict__ Bl,
         float* __restrict__ Cf, bf16* __restrict__ Ch, bf16* __restrict__ Cl,
         int Kdim, size_t sA, size_t sB, size_t sC, int ldC,
         const float* __restrict__ bias, const float* __restrict__ x2f,
         const float* __restrict__ ga, const float* __restrict__ be,
         const float* __restrict__ rm, const float* __restrict__ rv,
         const float* __restrict__ bt, float* __restrict__ rsum)
{
    constexpr int STG  = SPLIT ? 32768 : 16384;
    constexpr int BOFF = SPLIT ? 16384 : 8192;

    extern __shared__ __align__(128) char smem[];
    const uint32_t sb = smem_u32(smem);
    const int tid = threadIdx.x, wid = tid >> 5, lane = tid & 31;
    const int wm = wid & 1, wn = wid >> 1;
    const int bz = blockIdx.z;
    const int bsel = (EPI == 9 || EPI == 10) ? (bz & 15) : bz;
    const size_t rb = (size_t)Kdim * 2;

    const char *gAh, *gAl = nullptr, *gBh, *gBl = nullptr;
    if (EPI == 10) {
        const bf16* axh = (bz < 16) ? g_qTh : g_xTh;
        const bf16* axl = (bz < 16) ? g_qTl : g_xTl;
        gAh = (const char*)(axh + bsel * sA) + (size_t)(blockIdx.y * 128) * rb;
        gAl = (const char*)(axl + bsel * sA) + (size_t)(blockIdx.y * 128) * rb;
        const bf16* bxh = (bz < 16) ? g_Wqh : g_Wkh;
        const bf16* bxl = (bz < 16) ? g_Wql : g_Wkl;
        gBh = (const char*)bxh + (size_t)(blockIdx.x * 128) * rb;
        gBl = (const char*)bxl + (size_t)(blockIdx.x * 128) * rb;
    } else if (EPI == 9) {
        gAh = (const char*)Ah + (size_t)(blockIdx.y * 128) * rb;
        gAl = (const char*)Al + (size_t)(blockIdx.y * 128) * rb;
        const bf16* bxh = (bz < 16) ? g_qTh : g_xTh;
        const bf16* bxl = (bz < 16) ? g_qTl : g_xTl;
        gBh = (const char*)(bxh + bsel * sB) + (size_t)(blockIdx.x * 128) * rb;
        gBl = (const char*)(bxl + bsel * sB) + (size_t)(blockIdx.x * 128) * rb;
    } else {
        gAh = (const char*)(Ah + bz * sA) + (size_t)(blockIdx.y * 128) * rb;
        gBh = (const char*)(Bh + bz * sB) + (size_t)(blockIdx.x * 128) * rb;
        if (SPLIT) {
            gAl = (const char*)(Al + bz * sA) + (size_t)(blockIdx.y * 128) * rb;
            gBl = (const char*)(Bl + bz * sB) + (size_t)(blockIdx.x * 128) * rb;
        }
    }

    float acc[4][4][4];
    #pragma unroll
    for (int i = 0; i < 4; i++)
        #pragma unroll
        for (int j = 0; j < 4; j++)
            #pragma unroll
            for (int k = 0; k < 4; k++) acc[i][j][k] = 0.f;

    const int NC = Kdim >> 5;

    auto load_stage = [&](int s, int chunk) {
        const uint32_t base = sb + s * STG;
        const size_t cb = (size_t)chunk * 64;
        #pragma unroll
        for (int j = 0; j < 2; j++) {
            int idx = j * 256 + tid;
            int r = idx >> 2, c = (idx & 3) * 16;
            uint32_t off = SWZ64(r * 64 + c);
            size_t go = (size_t)r * rb + cb + c;
            cp16(base + off,        gAh + go);
            cp16(base + BOFF + off, gBh + go);
            if (SPLIT) {
                cp16(base + 8192 + off,  gAl + go);
                cp16(base + 24576 + off, gBl + go);
            }
        }
        CP_COMMIT();
    };

    load_stage(0, 0);
    load_stage(1, 1);

    for (int i = 0; i < NC; i++) {
        if (i + 1 < NC) { CP_WAIT1(); } else { CP_WAIT0(); }
        __syncthreads();
        if (i + 2 < NC) load_stage((i + 2) % 3, i + 2);   // buffer (i-1)%3: free
        const uint32_t aB = sb + (i % 3) * STG, bB = aB + BOFF;
        #pragma unroll
        for (int ks = 0; ks < 2; ks++) {
            uint32_t ah[4][4], al[4][4], bh[4][2], bl[4][2];
            #pragma unroll
            for (int ma = 0; ma < 4; ma++) {
                int row = wm * 64 + ma * 16 + (lane & 15);
                uint32_t off = SWZ64(row * 64 + ks * 32 + ((lane >> 4) * 16));
                ldsm4(ah[ma], aB + off);
                if (SPLIT) ldsm4(al[ma], aB + 8192 + off);
            }
            #pragma unroll
            for (int na = 0; na < 4; na++) {
                int row = wn * 32 + na * 8 + (lane & 7);
                uint32_t off = SWZ64(row * 64 + ks * 32 + (((lane >> 3) & 1) * 16));
                ldsm2(bh[na], bB + off);
                if (SPLIT) ldsm2(bl[na], bB + 8192 + off);
            }
            #pragma unroll
            for (int ma = 0; ma < 4; ma++)
                #pragma unroll
                for (int na = 0; na < 4; na++) {
                    mma16816<HALF>(acc[ma][na], ah[ma], bh[na]);
                    if (SPLIT) {
                        mma16816<HALF>(acc[ma][na], ah[ma], bl[na]);
                        mma16816<HALF>(acc[ma][na], al[ma], bh[na]);
                    }
                }
        }
    }

    // ---------------- epilogue ----------------
    const int g = lane >> 2, t = lane & 3;
    const int mB = blockIdx.y * 128 + wm * 64;
    const int nB = blockIdx.x * 128 + wn * 32;

    if (EPI == 7) {
        __syncthreads();
        uint32_t* stg = (uint32_t*)smem;   // stride 129
        #pragma unroll
        for (int ma = 0; ma < 4; ma++) {
            const int r0l = wm * 64 + ma * 16 + g;
            const int r1l = r0l + 8;
            float s0 = 0.f, s1 = 0.f;
            #pragma unroll
            for (int na = 0; na < 4; na++) {
                const int c0l = wn * 32 + na * 8 + 2 * t;
                const float* a = acc[ma][na];
                float p0 = __expf(fminf(a[0], 80.f));
                float p1 = __expf(fminf(a[1], 80.f));
                float p2 = __expf(fminf(a[2], 80.f));
                float p3 = __expf(fminf(a[3], 80.f));
                s0 += p0 + p1; s1 += p2 + p3;
                float h0 = __bfloat162float(__float2bfloat16(p0));
                float h1 = __bfloat162float(__float2bfloat16(p1));
                float h2 = __bfloat162float(__float2bfloat16(p2));
                float h3 = __bfloat162float(__float2bfloat16(p3));
                stg[r0l * 129 + c0l]     = pk(h0, p0 - h0);
                stg[r0l * 129 + c0l + 1] = pk(h1, p1 - h1);
                stg[r1l * 129 + c0l]     = pk(h2, p2 - h2);
                stg[r1l * 129 + c0l + 1] = pk(h3, p3 - h3);
            }
            s0 += __shfl_xor_sync(~0u, s0, 1); s0 += __shfl_xor_sync(~0u, s0, 2);
            s1 += __shfl_xor_sync(~0u, s1, 1); s1 += __shfl_xor_sync(~0u, s1, 2);
            if (t == 0) {
                atomicAdd(rsum + (size_t)bz * N_ + blockIdx.y * 128 + r0l, s0);
                atomicAdd(rsum + (size_t)bz * N_ + blockIdx.y * 128 + r1l, s1);
            }
        }
        __syncthreads();
        bf16* PThb = Ch + bz * sC;
        bf16* PTlb = Cl + bz * sC;
        const int rowBase = blockIdx.y * 128;
        const int colBase = blockIdx.x * 128;
        #pragma unroll
        for (int it = 0; it < 16; it++) {
            const int cloc = wid * 16 + it;
            uint32_t u0 = stg[(lane * 4 + 0) * 129 + cloc];
            uint32_t u1 = stg[(lane * 4 + 1) * 129 + cloc];
            uint32_t u2 = stg[(lane * 4 + 2) * 129 + cloc];
            uint32_t u3 = stg[(lane * 4 + 3) * 129 + cloc];
            uint32_t hp0 = (u0 & 0xFFFFu) | (u1 << 16);
            uint32_t hp1 = (u2 & 0xFFFFu) | (u3 << 16);
            uint32_t lp0 = (u0 >> 16) | (u1 & 0xFFFF0000u);
            uint32_t lp1 = (u2 >> 16) | (u3 & 0xFFFF0000u);
            size_t off = (size_t)(colBase + cloc) * ldC + rowBase + lane * 4;
            *(uint2*)(PThb + off) = make_uint2(hp0, hp1);
            *(uint2*)(PTlb + off) = make_uint2(lp0, lp1);
        }
        return;
    }

    if (EPI == 10) {
        bf16* Oh = ((bz < 16) ? g_QTh : g_KTh) + (size_t)bsel * sC;
        bf16* Ol = ((bz < 16) ? g_QTl : g_KTl) + (size_t)bsel * sC;
        #pragma unroll
        for (int ma = 0; ma < 4; ma++) {
            const int r0 = mB + ma * 16 + g, r1 = r0 + 8;
            #pragma unroll
            for (int na = 0; na < 4; na++) {
                const int c0 = nB + na * 8 + 2 * t;
                const float* a = acc[ma][na];
                const size_t o0 = (size_t)r0 * ldC + c0;
                const size_t o1 = (size_t)r1 * ldC + c0;
                float h0 = __bfloat162float(__float2bfloat16(a[0]));
                float h1 = __bfloat162float(__float2bfloat16(a[1]));
                float h2 = __bfloat162float(__float2bfloat16(a[2]));
                float h3 = __bfloat162float(__float2bfloat16(a[3]));
                *(uint32_t*)(Oh + o0) = pk(h0, h1);
                *(uint32_t*)(Ol + o0) = pk(a[0] - h0, a[1] - h1);
                *(uint32_t*)(Oh + o1) = pk(h2, h3);
                *(uint32_t*)(Ol + o1) = pk(a[2] - h2, a[3] - h3);
            }
        }
        return;
    }

    if (EPI == 9) {
        if (bz < 16) {
            __half* Ob = g_V16 + (size_t)bsel * sC;
            #pragma unroll
            for (int ma = 0; ma < 4; ma++) {
                const int r0 = mB + ma * 16 + g, r1 = r0 + 8;
                float p0 = bias[r0], p1 = bias[r1];
                #pragma unroll
                for (int na = 0; na < 4; na++) {
                    const int c0 = nB + na * 8 + 2 * t;
                    const float* a = acc[ma][na];
                    *(__half2*)(Ob + (size_t)r0 * ldC + c0) = __floats2half2_rn(a[0] + p0, a[1] + p0);
                    *(__half2*)(Ob + (size_t)r1 * ldC + c0) = __floats2half2_rn(a[2] + p1, a[3] + p1);
                }
            }
        } else {
            float* Ob = g_X2f + (size_t)bsel * sC;
            #pragma unroll
            for (int ma = 0; ma < 4; ma++) {
                const int r0 = mB + ma * 16 + g, r1 = r0 + 8;
                float p0 = bias[r0], p1 = bias[r1];
                #pragma unroll
                for (int na = 0; na < 4; na++) {
                    const int c0 = nB + na * 8 + 2 * t;
                    const float* a = acc[ma][na];
                    *(float2*)(Ob + (size_t)r0 * ldC + c0) = make_float2(a[0] + p0, a[1] + p0);
                    *(float2*)(Ob + (size_t)r1 * ldC + c0) = make_float2(a[2] + p1, a[3] + p1);
                }
            }
        }
        return;
    }

    float* Cfb = (EPI == 1 || EPI == 5) ? Cf + bz * sC : nullptr;
    bf16* Chb = (EPI == 6) ? Ch + bz * sC : nullptr;
    bf16* Clb = (EPI == 6) ? Cl + bz * sC : nullptr;
    const float* x2b = (EPI == 5 || EPI == 6) ? x2f + bz * sC : nullptr;

    #pragma unroll
    for (int ma = 0; ma < 4; ma++) {
        const int r0 = mB + ma * 16 + g;
        const int r1 = r0 + 8;
        float iv0 = 0.f, sh0 = 0.f, bo0 = 0.f;
        float iv1 = 0.f, sh1 = 0.f, bo1 = 0.f;
        if (EPI == 5) {
            iv0 = ga[r0] * rsqrtf(rv[r0] + BN_EPS);
            sh0 = be[r0] - rm[r0] * iv0; bo0 = bt[r0];
            iv1 = ga[r1] * rsqrtf(rv[r1] + BN_EPS);
            sh1 = be[r1] - rm[r1] * iv1; bo1 = bt[r1];
        }
        #pragma unroll
        for (int na = 0; na < 4; na++) {
            const int c0 = nB + na * 8 + 2 * t;
            const float* a = acc[ma][na];
            const size_t o0 = (size_t)r0 * ldC + c0;
            const size_t o1 = (size_t)r1 * ldC + c0;
            if (EPI == 1) {
                float b0 = bias[c0], b1 = bias[c0 + 1];
                *(float2*)(Cfb + o0) = make_float2(a[0] + b0, a[1] + b1);
                *(float2*)(Cfb + o1) = make_float2(a[2] + b0, a[3] + b1);
            } else if (EPI == 6) {
                float2 x0 = *(const float2*)(x2b + o0);
                float2 x1 = *(const float2*)(x2b + o1);
                float v0 = x0.x - a[0], v1 = x0.y - a[1];
                float v2 = x1.x - a[2], v3 = x1.y - a[3];
                float h0 = __bfloat162float(__float2bfloat16(v0));
                float h1 = __bfloat162float(__float2bfloat16(v1));
                float h2 = __bfloat162float(__float2bfloat16(v2));
                float h3 = __bfloat162float(__float2bfloat16(v3));
                *(uint32_t*)(Chb + o0) = pk(h0, h1);
                *(uint32_t*)(Clb + o0) = pk(v0 - h0, v1 - h1);
                *(uint32_t*)(Chb + o1) = pk(h2, h3);
                *(uint32_t*)(Clb + o1) = pk(v2 - h2, v3 - h3);
            } else { // EPI 5
                float2 x0 = *(const float2*)(x2b + o0);
                float2 x1 = *(const float2*)(x2b + o1);
                float2 w0, w1;
                w0.x = fmaxf((a[0] + bo0) * iv0 + sh0, 0.f) + x0.x;
                w0.y = fmaxf((a[1] + bo0) * iv0 + sh0, 0.f) + x0.y;
                w1.x = fmaxf((a[2] + bo1) * iv1 + sh1, 0.f) + x1.x;
                w1.y = fmaxf((a[3] + bo1) * iv1 + sh1, 0.f) + x1.y;
                *(float2*)(Cfb + o0) = w0;
                *(float2*)(Cfb + o1) = w1;
            }
        }
    }
}

// ---------------- aux kernels ----------------------------------------------
// all four weight splits in one launch (131072 elements)
__global__ void splitw_all(const float* __restrict__ Wq, const float* __restrict__ Wk,
                           const float* __restrict__ Wv, const float* __restrict__ Wt)
{
    int i = blockIdx.x * 256 + threadIdx.x;
    const float* src; bf16 *h, *l; int off;
    if (i < 16384)      { src = Wq; h = g_Wqh; l = g_Wql; off = i; }
    else if (i < 32768) { src = Wk; h = g_Wkh; l = g_Wkl; off = i - 16384; }
    else if (i < 65536) { src = Wv; h = g_Wvh; l = g_Wvl; off = i - 32768; }
    else                { src = Wt; h = g_Wth; l = g_Wtl; off = i - 65536; }
    float v = src[off];
    bf16 hv = __float2bfloat16(v);
    h[off] = hv;
    l[off] = __float2bfloat16(v - __bfloat162float(hv));
}

// transpose+split q and x in one launch (z = 32)
__global__ void tsplit2(const float* __restrict__ q, const float* __restrict__ x)
{
    __shared__ float sm[32][33];
    const int bz = blockIdx.z;
    const int b = bz & 15;
    const float* ip = ((bz < 16) ? q : x) + (size_t)b * C2_ * N_;
    bf16* oph = ((bz < 16) ? g_qTh : g_xTh) + (size_t)b * N_ * C2_;
    bf16* opl = ((bz < 16) ? g_qTl : g_xTl) + (size_t)b * N_ * C2_;
    const int n0 = blockIdx.x * 32, c0 = blockIdx.y * 32;
    const int r = threadIdx.x >> 5, c = threadIdx.x & 31;
    #pragma unroll
    for (int k = 0; k < 4; k++)
        sm[r + 8*k][c] = ip[(size_t)(c0 + r + 8*k) * N_ + n0 + c];
    __syncthreads();
    #pragma unroll
    for (int k = 0; k < 4; k++) {
        float v = sm[c][r + 8*k];
        bf16 hv = __float2bfloat16(v);
        size_t o = (size_t)(n0 + r + 8*k) * C2_ + c0 + c;
        oph[o] = hv;
        opl[o] = __float2bfloat16(v - __bfloat162float(hv));
    }
}

__global__ void zero_k(float* p, int n)
{
    int i = blockIdx.x * 256 + threadIdx.x;
    if (i < n) p[i] = 0.f;
}

__global__ void rinvk(const float* __restrict__ rs, float* __restrict__ ri, int n)
{
    int i = blockIdx.x * 256 + threadIdx.x;
    if (i < n) ri[i] = 1.f / rs[i];
}

// Per PT row m: cs = sum_n (Ph+Pl)*rinv[n]; S16[m][n] = (Ph+Pl)*rinv[n]/(1e-9+cs)
__global__ __launch_bounds__(256)
void normk(const bf16* __restrict__ pth, const bf16* __restrict__ ptl,
           const float* __restrict__ ri, __half* __restrict__ s16)
{
    const int wid = threadIdx.x >> 5, lane = threadIdx.x & 31;
    const size_t row = (size_t)blockIdx.x * 8 + wid;
    const bf16* ph = pth + row * N_;
    const bf16* pl = ptl + row * N_;
    const float* rv = ri + ((row >> 11) << 11);
    float v[64];
    float s = 0.f;
    #pragma unroll
    for (int k = 0; k < 8; k++) {
        int n0 = k * 256 + lane * 8;
        uint4 uh = *(const uint4*)(ph + n0);
        uint4 ul = *(const uint4*)(pl + n0);
        float4 r0 = *(const float4*)(rv + n0);
        float4 r1 = *(const float4*)(rv + n0 + 4);
        float rr[8];
        *(float4*)rr = r0; *(float4*)(rr + 4) = r1;
        const uint32_t* hw = (const uint32_t*)&uh;
        const uint32_t* lw = (const uint32_t*)&ul;
        #pragma unroll
        for (int j = 0; j < 4; j++) {
            float2 hv = __bfloat1622float2(*(const __nv_bfloat162*)&hw[j]);
            float2 lv = __bfloat1622float2(*(const __nv_bfloat162*)&lw[j]);
            float a = (hv.x + lv.x) * rr[2*j];
            float b = (hv.y + lv.y) * rr[2*j + 1];
            v[k*8 + 2*j] = a; v[k*8 + 2*j + 1] = b;
            s += a + b;
        }
    }
    #pragma unroll
    for (int o = 16; o > 0; o >>= 1) s += __shfl_xor_sync(~0u, s, o);
    const float inv = 1.f / (1e-9f + s);
    __half* op = s16 + row * N_;
    #pragma unroll
    for (int k = 0; k < 8; k++) {
        int n0 = k * 256 + lane * 8;
        __half2 h4[4];
        #pragma unroll
        for (int j = 0; j < 4; j++)
            h4[j] = __floats2half2_rn(v[k*8 + 2*j] * inv, v[k*8 + 2*j + 1] * inv);
        *(uint4*)(op + n0) = *(uint4*)h4;
    }
}

// ---------------- launcher -------------------------------------------------
extern "C" void kernel_launch(void* const* d_in, const int* in_sizes, int n_in,
                              void* d_out, int out_size)
{
    const float* q  = (const float*)d_in[0];
    const float* x  = (const float*)d_in[1];
    const float* Wq = (const float*)d_in[2];
    const float* Wk = (const float*)d_in[3];
    const float* Wv = (const float*)d_in[4];
    const float* bv = (const float*)d_in[5];
    const float* Wt = (const float*)d_in[6];
    const float* bt = (const float*)d_in[7];
    const float* ga = (const float*)d_in[8];
    const float* be = (const float*)d_in[9];
    const float* rm = (const float*)d_in[10];
    const float* rv = (const float*)d_in[11];
    float* out = (float*)d_out;

    #define SYM(T, p, s) T* p; cudaGetSymbolAddress((void**)&p, s)
    SYM(bf16, Wvh, g_Wvh); SYM(bf16, Wvl, g_Wvl);
    SYM(bf16, Wth, g_Wth); SYM(bf16, Wtl, g_Wtl);
    SYM(bf16, xTh, g_xTh); SYM(bf16, xTl, g_xTl);
    SYM(bf16, QTh, g_QTh); SYM(bf16, QTl, g_QTl);
    SYM(bf16, KTh, g_KTh); SYM(bf16, KTl, g_KTl);
    SYM(__half, V16, g_V16);
    SYM(float, X2T, g_X2T); SYM(float, X2f, g_X2f);
    SYM(float, rs, g_rs); SYM(float, ri, g_rinv);
    SYM(bf16, PTh, g_PTh); SYM(bf16, PTl, g_PTl);
    SYM(__half, S16, g_S16);
    SYM(bf16, D2h, g_D2h); SYM(bf16, D2l, g_D2l);
    #undef SYM

    const int SMB_S = 3 * 32768;   // 98304: split kernels, 3-stage
    const int SMB_H = 3 * 16384;   // 49152: fp16 single kernel
    cudaFuncSetAttribute(mmk<1,1,0>,  cudaFuncAttributeMaxDynamicSharedMemorySize, SMB_S);
    cudaFuncSetAttribute(mmk<5,1,0>,  cudaFuncAttributeMaxDynamicSharedMemorySize, SMB_S);
    cudaFuncSetAttribute(mmk<7,1,0>,  cudaFuncAttributeMaxDynamicSharedMemorySize, SMB_S);
    cudaFuncSetAttribute(mmk<9,1,0>,  cudaFuncAttributeMaxDynamicSharedMemorySize, SMB_S);
    cudaFuncSetAttribute(mmk<10,1,0>, cudaFuncAttributeMaxDynamicSharedMemorySize, SMB_S);
    cudaFuncSetAttribute(mmk<6,0,1>,  cudaFuncAttributeMaxDynamicSharedMemorySize, SMB_H);

    const size_t s2 = (size_t)N_ * C2_;
    const size_t sv = (size_t)C_ * N_;
    const size_t sx = (size_t)N_ * C_;
    const size_t se = (size_t)N_ * N_;

    zero_k<<<(B_*N_+255)/256, 256>>>(rs, B_*N_);
    splitw_all<<<512, 256>>>(Wq, Wk, Wv, Wt);
    tsplit2<<<dim3(N_/32, C2_/32, 2*B_), 256>>>(q, x);

    // merged QK projections (z=32: bz<16 -> QT, else KT)
    mmk<10,1,0><<<dim3(1,16,2*B_), 256, SMB_S>>>(nullptr, nullptr, nullptr, nullptr,
        nullptr, nullptr, nullptr, C2_, s2, 0, s2, C2_,
        nullptr, nullptr, nullptr, nullptr, nullptr, nullptr, nullptr, nullptr);
    // merged V16 (fp16) / X2f (f32) projections (z=32)
    mmk<9,1,0><<<dim3(16,2,2*B_), 256, SMB_S>>>(Wvh, Wvl, nullptr, nullptr,
        nullptr, nullptr, nullptr, C2_, 0, s2, sv, N_,
        bv, nullptr, nullptr, nullptr, nullptr, nullptr, nullptr, nullptr);
    // X2T[n][c] = xT*Wv^T + bv[col]
    mmk<1,1,0><<<dim3(2,16,B_), 256, SMB_S>>>(xTh, xTl, Wvh, Wvl, X2T, nullptr, nullptr,
        C2_, s2, 0, sx, C_, bv, nullptr, nullptr, nullptr, nullptr, nullptr, nullptr, nullptr);
    // E-GEMM -> PT hi/lo + rowsums
    mmk<7,1,0><<<dim3(16,16,B_), 256, SMB_S>>>(QTh, QTl, KTh, KTl, nullptr, PTh, PTl,
        C2_, s2, s2, se, N_, nullptr, nullptr, nullptr, nullptr, nullptr, nullptr, nullptr, rs);
    // rinv; fully-normalized S16 (fp16)
    rinvk<<<(B_*N_+255)/256, 256>>>(rs, ri, B_*N_);
    normk<<<B_*N_/8, 256>>>(PTh, PTl, ri, S16);
    // XR GEMM (single fp16) -> D2 = split(X2T - acc)
    mmk<6,0,1><<<dim3(2,16,B_), 256, SMB_H>>>((const bf16*)S16, nullptr, (const bf16*)V16, nullptr,
        nullptr, D2h, D2l, N_, se, sv, sx, C_, nullptr, X2T, nullptr, nullptr, nullptr, nullptr, nullptr, nullptr);
    // out[c][n] = relu(bn(Wt*D2 + bt)) + X2f
    mmk<5,1,0><<<dim3(16,2,B_), 256, SMB_S>>>(Wth, Wtl, D2h, D2l, out, nullptr, nullptr,
        C_, 0, sx, sv, N_, nullptr, X2f, ga, be, rm, rv, bt, nullptr);
}

// round 16
// speedup vs baseline: 3.1599x; 1.2336x over previous
#include <cuda_runtime.h>
#include <cuda_bf16.h>
#include <cuda_fp16.h>
#include <cstdint>

#define B_  16
#define C_  256
#define C2_ 128
#define N_  2048
#define BN_EPS 1e-5f
typedef __nv_bfloat16 bf16;

// ---------------- scratch (device globals) ---------------------------------
__device__ __align__(128) bf16 g_qTh[(size_t)B_*N_*C2_], g_qTl[(size_t)B_*N_*C2_];
__device__ __align__(128) bf16 g_xTh[(size_t)B_*N_*C2_], g_xTl[(size_t)B_*N_*C2_];
__device__ __align__(128) bf16 g_Wqh[C2_*C2_], g_Wql[C2_*C2_];
__device__ __align__(128) bf16 g_Wkh[C2_*C2_], g_Wkl[C2_*C2_];
__device__ __align__(128) bf16 g_Wvh[C_*C2_],  g_Wvl[C_*C2_];
__device__ __align__(128) bf16 g_Wth[C_*C_],   g_Wtl[C_*C_];
__device__ __align__(128) bf16 g_QTh[(size_t)B_*N_*C2_], g_QTl[(size_t)B_*N_*C2_];
__device__ __align__(128) bf16 g_KTh[(size_t)B_*N_*C2_], g_KTl[(size_t)B_*N_*C2_];
__device__ __align__(128) __half g_V16[(size_t)B_*C_*N_];
__device__ __align__(128) float g_X2T[(size_t)B_*N_*C_];
__device__ __align__(128) float g_X2f[(size_t)B_*C_*N_];
__device__ __align__(128) float g_rs[(size_t)B_*N_], g_rinv[(size_t)B_*N_];
__device__ __align__(128) bf16 g_PTh[(size_t)B_*N_*N_], g_PTl[(size_t)B_*N_*N_];
__device__ __align__(128) __half g_S16[(size_t)B_*N_*N_];
__device__ __align__(128) bf16 g_D2h[(size_t)B_*N_*C_], g_D2l[(size_t)B_*N_*C_];

// ---------------- helpers --------------------------------------------------
__device__ __forceinline__ uint32_t smem_u32(const void* p) {
    uint32_t a;
    asm("{ .reg .u64 t; cvta.to.shared.u64 t, %1; cvt.u32.u64 %0, t; }" : "=r"(a) : "l"(p));
    return a;
}
#define SWZ64(x) ((x) ^ (((x) >> 3) & 0x30))
#define CP_COMMIT() asm volatile("cp.async.commit_group;" ::: "memory")
#define CP_WAIT1()  asm volatile("cp.async.wait_group 1;" ::: "memory")
#define CP_WAIT0()  asm volatile("cp.async.wait_group 0;" ::: "memory")

__device__ __forceinline__ void cp16(uint32_t dst, const void* src) {
    asm volatile("cp.async.cg.shared.global [%0], [%1], 16;" :: "r"(dst), "l"(src));
}
__device__ __forceinline__ void ldsm4(uint32_t* r, uint32_t a) {
    asm volatile("ldmatrix.sync.aligned.m8n8.x4.shared.b16 {%0,%1,%2,%3}, [%4];"
        : "=r"(r[0]), "=r"(r[1]), "=r"(r[2]), "=r"(r[3]) : "r"(a));
}
__device__ __forceinline__ void ldsm2(uint32_t* r, uint32_t a) {
    asm volatile("ldmatrix.sync.aligned.m8n8.x2.shared.b16 {%0,%1}, [%2];"
        : "=r"(r[0]), "=r"(r[1]) : "r"(a));
}
template<int HALF>
__device__ __forceinline__ void mma16816(float* d, const uint32_t* a, const uint32_t* b) {
    if (HALF)
        asm volatile("mma.sync.aligned.m16n8k16.row.col.f32.f16.f16.f32 "
            "{%0,%1,%2,%3}, {%4,%5,%6,%7}, {%8,%9}, {%0,%1,%2,%3};"
            : "+f"(d[0]), "+f"(d[1]), "+f"(d[2]), "+f"(d[3])
            : "r"(a[0]), "r"(a[1]), "r"(a[2]), "r"(a[3]), "r"(b[0]), "r"(b[1]));
    else
        asm volatile("mma.sync.aligned.m16n8k16.row.col.f32.bf16.bf16.f32 "
            "{%0,%1,%2,%3}, {%4,%5,%6,%7}, {%8,%9}, {%0,%1,%2,%3};"
            : "+f"(d[0]), "+f"(d[1]), "+f"(d[2]), "+f"(d[3])
            : "r"(a[0]), "r"(a[1]), "r"(a[2]), "r"(a[3]), "r"(b[0]), "r"(b[1]));
}
__device__ __forceinline__ uint32_t pk(float a, float b) {
    __nv_bfloat162 t = __floats2bfloat162_rn(a, b);
    return *reinterpret_cast<uint32_t*>(&t);
}

// ---------------- warp-MMA GEMM --------------------------------------------
// C[M, Np] = A[M,K] * B[Np,K]^T, K-major 16-bit operands.
// SPLIT=1: hi/lo pairs, 3-term split product. Tile 128x128, Kc=32,
// 3-buffer cp.async pipeline (single sync/iter), 8 warps of 64x32,
// 2 CTAs/SM (regs capped at 128; B-frags first, A-frags per-row).
// EPI: 1 f32+bias[col] | 5 final relu(bn)+x2 | 6 XR: split(x2t - acc)
//      7 E: exp + transposed hi/lo + rowsums | 9 merged V16(fp16)/X2f(f32)
//      10 merged QK split-out
template<int EPI, int SPLIT, int HALF>
__global__ __launch_bounds__(256, 2)
void mmk(const bf16* __restrict__ Ah, const bf16* __restrict__ Al,
         const bf16* __restrict__ Bh, const bf16* __restrict__ Bl,
         float* __restrict__ Cf, bf16* __restrict__ Ch, bf16* __restrict__ Cl,
         int Kdim, size_t sA, size_t sB, size_t sC, int ldC,
         const float* __restrict__ bias, const float* __restrict__ x2f,
         const float* __restrict__ ga, const float* __restrict__ be,
         const float* __restrict__ rm, const float* __restrict__ rv,
         const float* __restrict__ bt, float* __restrict__ rsum)
{
    constexpr int STG  = SPLIT ? 32768 : 16384;
    constexpr int BOFF = SPLIT ? 16384 : 8192;

    extern __shared__ __align__(128) char smem[];
    const uint32_t sb = smem_u32(smem);
    const int tid = threadIdx.x, wid = tid >> 5, lane = tid & 31;
    const int wm = wid & 1, wn = wid >> 1;
    const int bz = blockIdx.z;
    const int bsel = (EPI == 9 || EPI == 10) ? (bz & 15) : bz;
    const size_t rb = (size_t)Kdim * 2;

    const char *gAh, *gAl = nullptr, *gBh, *gBl = nullptr;
    if (EPI == 10) {
        const bf16* axh = (bz < 16) ? g_qTh : g_xTh;
        const bf16* axl = (bz < 16) ? g_qTl : g_xTl;
        gAh = (const char*)(axh + bsel * sA) + (size_t)(blockIdx.y * 128) * rb;
        gAl = (const char*)(axl + bsel * sA) + (size_t)(blockIdx.y * 128) * rb;
        const bf16* bxh = (bz < 16) ? g_Wqh : g_Wkh;
        const bf16* bxl = (bz < 16) ? g_Wql : g_Wkl;
        gBh = (const char*)bxh + (size_t)(blockIdx.x * 128) * rb;
        gBl = (const char*)bxl + (size_t)(blockIdx.x * 128) * rb;
    } else if (EPI == 9) {
        gAh = (const char*)Ah + (size_t)(blockIdx.y * 128) * rb;
        gAl = (const char*)Al + (size_t)(blockIdx.y * 128) * rb;
        const bf16* bxh = (bz < 16) ? g_qTh : g_xTh;
        const bf16* bxl = (bz < 16) ? g_qTl : g_xTl;
        gBh = (const char*)(bxh + bsel * sB) + (size_t)(blockIdx.x * 128) * rb;
        gBl = (const char*)(bxl + bsel * sB) + (size_t)(blockIdx.x * 128) * rb;
    } else {
        gAh = (const char*)(Ah + bz * sA) + (size_t)(blockIdx.y * 128) * rb;
        gBh = (const char*)(Bh + bz * sB) + (size_t)(blockIdx.x * 128) * rb;
        if (SPLIT) {
            gAl = (const char*)(Al + bz * sA) + (size_t)(blockIdx.y * 128) * rb;
            gBl = (const char*)(Bl + bz * sB) + (size_t)(blockIdx.x * 128) * rb;
        }
    }

    float acc[4][4][4];
    #pragma unroll
    for (int i = 0; i < 4; i++)
        #pragma unroll
        for (int j = 0; j < 4; j++)
            #pragma unroll
            for (int k = 0; k < 4; k++) acc[i][j][k] = 0.f;

    const int NC = Kdim >> 5;

    auto load_stage = [&](int s, int chunk) {
        const uint32_t base = sb + s * STG;
        const size_t cb = (size_t)chunk * 64;
        #pragma unroll
        for (int j = 0; j < 2; j++) {
            int idx = j * 256 + tid;
            int r = idx >> 2, c = (idx & 3) * 16;
            uint32_t off = SWZ64(r * 64 + c);
            size_t go = (size_t)r * rb + cb + c;
            cp16(base + off,        gAh + go);
            cp16(base + BOFF + off, gBh + go);
            if (SPLIT) {
                cp16(base + 8192 + off,  gAl + go);
                cp16(base + 24576 + off, gBl + go);
            }
        }
        CP_COMMIT();
    };

    load_stage(0, 0);
    load_stage(1, 1);

    for (int i = 0; i < NC; i++) {
        if (i + 1 < NC) { CP_WAIT1(); } else { CP_WAIT0(); }
        __syncthreads();
        if (i + 2 < NC) load_stage((i + 2) % 3, i + 2);   // buffer (i-1)%3: free
        const uint32_t aB = sb + (i % 3) * STG, bB = aB + BOFF;
        #pragma unroll
        for (int ks = 0; ks < 2; ks++) {
            uint32_t bh[4][2], bl[4][2];
            #pragma unroll
            for (int na = 0; na < 4; na++) {
                int row = wn * 32 + na * 8 + (lane & 7);
                uint32_t off = SWZ64(row * 64 + ks * 32 + (((lane >> 3) & 1) * 16));
                ldsm2(bh[na], bB + off);
                if (SPLIT) ldsm2(bl[na], bB + 8192 + off);
            }
            #pragma unroll
            for (int ma = 0; ma < 4; ma++) {
                uint32_t ah[4], al[4];
                int row = wm * 64 + ma * 16 + (lane & 15);
                uint32_t off = SWZ64(row * 64 + ks * 32 + ((lane >> 4) * 16));
                ldsm4(ah, aB + off);
                if (SPLIT) ldsm4(al, aB + 8192 + off);
                #pragma unroll
                for (int na = 0; na < 4; na++) {
                    mma16816<HALF>(acc[ma][na], ah, bh[na]);
                    if (SPLIT) {
                        mma16816<HALF>(acc[ma][na], ah, bl[na]);
                        mma16816<HALF>(acc[ma][na], al, bh[na]);
                    }
                }
            }
        }
    }

    // ---------------- epilogue ----------------
    const int g = lane >> 2, t = lane & 3;
    const int mB = blockIdx.y * 128 + wm * 64;
    const int nB = blockIdx.x * 128 + wn * 32;

    if (EPI == 7) {
        __syncthreads();
        uint32_t* stg = (uint32_t*)smem;   // stride 129
        #pragma unroll
        for (int ma = 0; ma < 4; ma++) {
            const int r0l = wm * 64 + ma * 16 + g;
            const int r1l = r0l + 8;
            float s0 = 0.f, s1 = 0.f;
            #pragma unroll
            for (int na = 0; na < 4; na++) {
                const int c0l = wn * 32 + na * 8 + 2 * t;
                const float* a = acc[ma][na];
                float p0 = __expf(fminf(a[0], 80.f));
                float p1 = __expf(fminf(a[1], 80.f));
                float p2 = __expf(fminf(a[2], 80.f));
                float p3 = __expf(fminf(a[3], 80.f));
                s0 += p0 + p1; s1 += p2 + p3;
                float h0 = __bfloat162float(__float2bfloat16(p0));
                float h1 = __bfloat162float(__float2bfloat16(p1));
                float h2 = __bfloat162float(__float2bfloat16(p2));
                float h3 = __bfloat162float(__float2bfloat16(p3));
                stg[r0l * 129 + c0l]     = pk(h0, p0 - h0);
                stg[r0l * 129 + c0l + 1] = pk(h1, p1 - h1);
                stg[r1l * 129 + c0l]     = pk(h2, p2 - h2);
                stg[r1l * 129 + c0l + 1] = pk(h3, p3 - h3);
            }
            s0 += __shfl_xor_sync(~0u, s0, 1); s0 += __shfl_xor_sync(~0u, s0, 2);
            s1 += __shfl_xor_sync(~0u, s1, 1); s1 += __shfl_xor_sync(~0u, s1, 2);
            if (t == 0) {
                atomicAdd(rsum + (size_t)bz * N_ + blockIdx.y * 128 + r0l, s0);
                atomicAdd(rsum + (size_t)bz * N_ + blockIdx.y * 128 + r1l, s1);
            }
        }
        __syncthreads();
        bf16* PThb = Ch + bz * sC;
        bf16* PTlb = Cl + bz * sC;
        const int rowBase = blockIdx.y * 128;
        const int colBase = blockIdx.x * 128;
        #pragma unroll
        for (int it = 0; it < 16; it++) {
            const int cloc = wid * 16 + it;
            uint32_t u0 = stg[(lane * 4 + 0) * 129 + cloc];
            uint32_t u1 = stg[(lane * 4 + 1) * 129 + cloc];
            uint32_t u2 = stg[(lane * 4 + 2) * 129 + cloc];
            uint32_t u3 = stg[(lane * 4 + 3) * 129 + cloc];
            uint32_t hp0 = (u0 & 0xFFFFu) | (u1 << 16);
            uint32_t hp1 = (u2 & 0xFFFFu) | (u3 << 16);
            uint32_t lp0 = (u0 >> 16) | (u1 & 0xFFFF0000u);
            uint32_t lp1 = (u2 >> 16) | (u3 & 0xFFFF0000u);
            size_t off = (size_t)(colBase + cloc) * ldC + rowBase + lane * 4;
            *(uint2*)(PThb + off) = make_uint2(hp0, hp1);
            *(uint2*)(PTlb + off) = make_uint2(lp0, lp1);
        }
        return;
    }

    if (EPI == 10) {
        bf16* Oh = ((bz < 16) ? g_QTh : g_KTh) + (size_t)bsel * sC;
        bf16* Ol = ((bz < 16) ? g_QTl : g_KTl) + (size_t)bsel * sC;
        #pragma unroll
        for (int ma = 0; ma < 4; ma++) {
            const int r0 = mB + ma * 16 + g, r1 = r0 + 8;
            #pragma unroll
            for (int na = 0; na < 4; na++) {
                const int c0 = nB + na * 8 + 2 * t;
                const float* a = acc[ma][na];
                const size_t o0 = (size_t)r0 * ldC + c0;
                const size_t o1 = (size_t)r1 * ldC + c0;
                float h0 = __bfloat162float(__float2bfloat16(a[0]));
                float h1 = __bfloat162float(__float2bfloat16(a[1]));
                float h2 = __bfloat162float(__float2bfloat16(a[2]));
                float h3 = __bfloat162float(__float2bfloat16(a[3]));
                *(uint32_t*)(Oh + o0) = pk(h0, h1);
                *(uint32_t*)(Ol + o0) = pk(a[0] - h0, a[1] - h1);
                *(uint32_t*)(Oh + o1) = pk(h2, h3);
                *(uint32_t*)(Ol + o1) = pk(a[2] - h2, a[3] - h3);
            }
        }
        return;
    }

    if (EPI == 9) {
        if (bz < 16) {
            __half* Ob = g_V16 + (size_t)bsel * sC;
            #pragma unroll
            for (int ma = 0; ma < 4; ma++) {
                const int r0 = mB + ma * 16 + g, r1 = r0 + 8;
                float p0 = bias[r0], p1 = bias[r1];
                #pragma unroll
                for (int na = 0; na < 4; na++) {
                    const int c0 = nB + na * 8 + 2 * t;
                    const float* a = acc[ma][na];
                    *(__half2*)(Ob + (size_t)r0 * ldC + c0) = __floats2half2_rn(a[0] + p0, a[1] + p0);
                    *(__half2*)(Ob + (size_t)r1 * ldC + c0) = __floats2half2_rn(a[2] + p1, a[3] + p1);
                }
            }
        } else {
            float* Ob = g_X2f + (size_t)bsel * sC;
            #pragma unroll
            for (int ma = 0; ma < 4; ma++) {
                const int r0 = mB + ma * 16 + g, r1 = r0 + 8;
                float p0 = bias[r0], p1 = bias[r1];
                #pragma unroll
                for (int na = 0; na < 4; na++) {
                    const int c0 = nB + na * 8 + 2 * t;
                    const float* a = acc[ma][na];
                    *(float2*)(Ob + (size_t)r0 * ldC + c0) = make_float2(a[0] + p0, a[1] + p0);
                    *(float2*)(Ob + (size_t)r1 * ldC + c0) = make_float2(a[2] + p1, a[3] + p1);
                }
            }
        }
        return;
    }

    float* Cfb = (EPI == 1 || EPI == 5) ? Cf + bz * sC : nullptr;
    bf16* Chb = (EPI == 6) ? Ch + bz * sC : nullptr;
    bf16* Clb = (EPI == 6) ? Cl + bz * sC : nullptr;
    const float* x2b = (EPI == 5 || EPI == 6) ? x2f + bz * sC : nullptr;

    #pragma unroll
    for (int ma = 0; ma < 4; ma++) {
        const int r0 = mB + ma * 16 + g;
        const int r1 = r0 + 8;
        float iv0 = 0.f, sh0 = 0.f, bo0 = 0.f;
        float iv1 = 0.f, sh1 = 0.f, bo1 = 0.f;
        if (EPI == 5) {
            iv0 = ga[r0] * rsqrtf(rv[r0] + BN_EPS);
            sh0 = be[r0] - rm[r0] * iv0; bo0 = bt[r0];
            iv1 = ga[r1] * rsqrtf(rv[r1] + BN_EPS);
            sh1 = be[r1] - rm[r1] * iv1; bo1 = bt[r1];
        }
        #pragma unroll
        for (int na = 0; na < 4; na++) {
            const int c0 = nB + na * 8 + 2 * t;
            const float* a = acc[ma][na];
            const size_t o0 = (size_t)r0 * ldC + c0;
            const size_t o1 = (size_t)r1 * ldC + c0;
            if (EPI == 1) {
                float b0 = bias[c0], b1 = bias[c0 + 1];
                *(float2*)(Cfb + o0) = make_float2(a[0] + b0, a[1] + b1);
                *(float2*)(Cfb + o1) = make_float2(a[2] + b0, a[3] + b1);
            } else if (EPI == 6) {
                float2 x0 = *(const float2*)(x2b + o0);
                float2 x1 = *(const float2*)(x2b + o1);
                float v0 = x0.x - a[0], v1 = x0.y - a[1];
                float v2 = x1.x - a[2], v3 = x1.y - a[3];
                float h0 = __bfloat162float(__float2bfloat16(v0));
                float h1 = __bfloat162float(__float2bfloat16(v1));
                float h2 = __bfloat162float(__float2bfloat16(v2));
                float h3 = __bfloat162float(__float2bfloat16(v3));
                *(uint32_t*)(Chb + o0) = pk(h0, h1);
                *(uint32_t*)(Clb + o0) = pk(v0 - h0, v1 - h1);
                *(uint32_t*)(Chb + o1) = pk(h2, h3);
                *(uint32_t*)(Clb + o1) = pk(v2 - h2, v3 - h3);
            } else { // EPI 5
                float2 x0 = *(const float2*)(x2b + o0);
                float2 x1 = *(const float2*)(x2b + o1);
                float2 w0, w1;
                w0.x = fmaxf((a[0] + bo0) * iv0 + sh0, 0.f) + x0.x;
                w0.y = fmaxf((a[1] + bo0) * iv0 + sh0, 0.f) + x0.y;
                w1.x = fmaxf((a[2] + bo1) * iv1 + sh1, 0.f) + x1.x;
                w1.y = fmaxf((a[3] + bo1) * iv1 + sh1, 0.f) + x1.y;
                *(float2*)(Cfb + o0) = w0;
                *(float2*)(Cfb + o1) = w1;
            }
        }
    }
}

// ---------------- aux kernels ----------------------------------------------
__global__ void splitw_all(const float* __restrict__ Wq, const float* __restrict__ Wk,
                           const float* __restrict__ Wv, const float* __restrict__ Wt)
{
    int i = blockIdx.x * 256 + threadIdx.x;
    const float* src; bf16 *h, *l; int off;
    if (i < 16384)      { src = Wq; h = g_Wqh; l = g_Wql; off = i; }
    else if (i < 32768) { src = Wk; h = g_Wkh; l = g_Wkl; off = i - 16384; }
    else if (i < 65536) { src = Wv; h = g_Wvh; l = g_Wvl; off = i - 32768; }
    else                { src = Wt; h = g_Wth; l = g_Wtl; off = i - 65536; }
    float v = src[off];
    bf16 hv = __float2bfloat16(v);
    h[off] = hv;
    l[off] = __float2bfloat16(v - __bfloat162float(hv));
}

__global__ void tsplit2(const float* __restrict__ q, const float* __restrict__ x)
{
    __shared__ float sm[32][33];
    const int bz = blockIdx.z;
    const int b = bz & 15;
    const float* ip = ((bz < 16) ? q : x) + (size_t)b * C2_ * N_;
    bf16* oph = ((bz < 16) ? g_qTh : g_xTh) + (size_t)b * N_ * C2_;
    bf16* opl = ((bz < 16) ? g_qTl : g_xTl) + (size_t)b * N_ * C2_;
    const int n0 = blockIdx.x * 32, c0 = blockIdx.y * 32;
    const int r = threadIdx.x >> 5, c = threadIdx.x & 31;
    #pragma unroll
    for (int k = 0; k < 4; k++)
        sm[r + 8*k][c] = ip[(size_t)(c0 + r + 8*k) * N_ + n0 + c];
    __syncthreads();
    #pragma unroll
    for (int k = 0; k < 4; k++) {
        float v = sm[c][r + 8*k];
        bf16 hv = __float2bfloat16(v);
        size_t o = (size_t)(n0 + r + 8*k) * C2_ + c0 + c;
        oph[o] = hv;
        opl[o] = __float2bfloat16(v - __bfloat162float(hv));
    }
}

__global__ void zero_k(float* p, int n)
{
    int i = blockIdx.x * 256 + threadIdx.x;
    if (i < n) p[i] = 0.f;
}

__global__ void rinvk(const float* __restrict__ rs, float* __restrict__ ri, int n)
{
    int i = blockIdx.x * 256 + threadIdx.x;
    if (i < n) ri[i] = 1.f / rs[i];
}

__global__ __launch_bounds__(256)
void normk(const bf16* __restrict__ pth, const bf16* __restrict__ ptl,
           const float* __restrict__ ri, __half* __restrict__ s16)
{
    const int wid = threadIdx.x >> 5, lane = threadIdx.x & 31;
    const size_t row = (size_t)blockIdx.x * 8 + wid;
    const bf16* ph = pth + row * N_;
    const bf16* pl = ptl + row * N_;
    const float* rv = ri + ((row >> 11) << 11);
    float v[64];
    float s = 0.f;
    #pragma unroll
    for (int k = 0; k < 8; k++) {
        int n0 = k * 256 + lane * 8;
        uint4 uh = *(const uint4*)(ph + n0);
        uint4 ul = *(const uint4*)(pl + n0);
        float4 r0 = *(const float4*)(rv + n0);
        float4 r1 = *(const float4*)(rv + n0 + 4);
        float rr[8];
        *(float4*)rr = r0; *(float4*)(rr + 4) = r1;
        const uint32_t* hw = (const uint32_t*)&uh;
        const uint32_t* lw = (const uint32_t*)&ul;
        #pragma unroll
        for (int j = 0; j < 4; j++) {
            float2 hv = __bfloat1622float2(*(const __nv_bfloat162*)&hw[j]);
            float2 lv = __bfloat1622float2(*(const __nv_bfloat162*)&lw[j]);
            float a = (hv.x + lv.x) * rr[2*j];
            float b = (hv.y + lv.y) * rr[2*j + 1];
            v[k*8 + 2*j] = a; v[k*8 + 2*j + 1] = b;
            s += a + b;
        }
    }
    #pragma unroll
    for (int o = 16; o > 0; o >>= 1) s += __shfl_xor_sync(~0u, s, o);
    const float inv = 1.f / (1e-9f + s);
    __half* op = s16 + row * N_;
    #pragma unroll
    for (int k = 0; k < 8; k++) {
        int n0 = k * 256 + lane * 8;
        __half2 h4[4];
        #pragma unroll
        for (int j = 0; j < 4; j++)
            h4[j] = __floats2half2_rn(v[k*8 + 2*j] * inv, v[k*8 + 2*j + 1] * inv);
        *(uint4*)(op + n0) = *(uint4*)h4;
    }
}

// ---------------- launcher -------------------------------------------------
extern "C" void kernel_launch(void* const* d_in, const int* in_sizes, int n_in,
                              void* d_out, int out_size)
{
    const float* q  = (const float*)d_in[0];
    const float* x  = (const float*)d_in[1];
    const float* Wq = (const float*)d_in[2];
    const float* Wk = (const float*)d_in[3];
    const float* Wv = (const float*)d_in[4];
    const float* bv = (const float*)d_in[5];
    const float* Wt = (const float*)d_in[6];
    const float* bt = (const float*)d_in[7];
    const float* ga = (const float*)d_in[8];
    const float* be = (const float*)d_in[9];
    const float* rm = (const float*)d_in[10];
    const float* rv = (const float*)d_in[11];
    float* out = (float*)d_out;

    #define SYM(T, p, s) T* p; cudaGetSymbolAddress((void**)&p, s)
    SYM(bf16, Wvh, g_Wvh); SYM(bf16, Wvl, g_Wvl);
    SYM(bf16, Wth, g_Wth); SYM(bf16, Wtl, g_Wtl);
    SYM(bf16, xTh, g_xTh); SYM(bf16, xTl, g_xTl);
    SYM(bf16, QTh, g_QTh); SYM(bf16, QTl, g_QTl);
    SYM(bf16, KTh, g_KTh); SYM(bf16, KTl, g_KTl);
    SYM(__half, V16, g_V16);
    SYM(float, X2T, g_X2T); SYM(float, X2f, g_X2f);
    SYM(float, rs, g_rs); SYM(float, ri, g_rinv);
    SYM(bf16, PTh, g_PTh); SYM(bf16, PTl, g_PTl);
    SYM(__half, S16, g_S16);
    SYM(bf16, D2h, g_D2h); SYM(bf16, D2l, g_D2l);
    #undef SYM

    const int SMB_S = 3 * 32768;   // 98304: split kernels, 3-stage
    const int SMB_H = 3 * 16384;   // 49152: fp16 single kernel
    cudaFuncSetAttribute(mmk<1,1,0>,  cudaFuncAttributeMaxDynamicSharedMemorySize, SMB_S);
    cudaFuncSetAttribute(mmk<5,1,0>,  cudaFuncAttributeMaxDynamicSharedMemorySize, SMB_S);
    cudaFuncSetAttribute(mmk<7,1,0>,  cudaFuncAttributeMaxDynamicSharedMemorySize, SMB_S);
    cudaFuncSetAttribute(mmk<9,1,0>,  cudaFuncAttributeMaxDynamicSharedMemorySize, SMB_S);
    cudaFuncSetAttribute(mmk<10,1,0>, cudaFuncAttributeMaxDynamicSharedMemorySize, SMB_S);
    cudaFuncSetAttribute(mmk<6,0,1>,  cudaFuncAttributeMaxDynamicSharedMemorySize, SMB_H);

    const size_t s2 = (size_t)N_ * C2_;
    const size_t sv = (size_t)C_ * N_;
    const size_t sx = (size_t)N_ * C_;
    const size_t se = (size_t)N_ * N_;

    zero_k<<<(B_*N_+255)/256, 256>>>(rs, B_*N_);
    splitw_all<<<512, 256>>>(Wq, Wk, Wv, Wt);
    tsplit2<<<dim3(N_/32, C2_/32, 2*B_), 256>>>(q, x);

    // merged QK projections (z=32: bz<16 -> QT, else KT)
    mmk<10,1,0><<<dim3(1,16,2*B_), 256, SMB_S>>>(nullptr, nullptr, nullptr, nullptr,
        nullptr, nullptr, nullptr, C2_, s2, 0, s2, C2_,
        nullptr, nullptr, nullptr, nullptr, nullptr, nullptr, nullptr, nullptr);
    // merged V16 (fp16) / X2f (f32) projections (z=32)
    mmk<9,1,0><<<dim3(16,2,2*B_), 256, SMB_S>>>(Wvh, Wvl, nullptr, nullptr,
        nullptr, nullptr, nullptr, C2_, 0, s2, sv, N_,
        bv, nullptr, nullptr, nullptr, nullptr, nullptr, nullptr, nullptr);
    // X2T[n][c] = xT*Wv^T + bv[col]
    mmk<1,1,0><<<dim3(2,16,B_), 256, SMB_S>>>(xTh, xTl, Wvh, Wvl, X2T, nullptr, nullptr,
        C2_, s2, 0, sx, C_, bv, nullptr, nullptr, nullptr, nullptr, nullptr, nullptr, nullptr);
    // E-GEMM -> PT hi/lo + rowsums
    mmk<7,1,0><<<dim3(16,16,B_), 256, SMB_S>>>(QTh, QTl, KTh, KTl, nullptr, PTh, PTl,
        C2_, s2, s2, se, N_, nullptr, nullptr, nullptr, nullptr, nullptr, nullptr, nullptr, rs);
    // rinv; fully-normalized S16 (fp16)
    rinvk<<<(B_*N_+255)/256, 256>>>(rs, ri, B_*N_);
    normk<<<B_*N_/8, 256>>>(PTh, PTl, ri, S16);
    // XR GEMM (single fp16) -> D2 = split(X2T - acc)
    mmk<6,0,1><<<dim3(2,16,B_), 256, SMB_H>>>((const bf16*)S16, nullptr, (const bf16*)V16, nullptr,
        nullptr, D2h, D2l, N_, se, sv, sx, C_, nullptr, X2T, nullptr, nullptr, nullptr, nullptr, nullptr, nullptr);
    // out[c][n] = relu(bn(Wt*D2 + bt)) + X2f
    mmk<5,1,0><<<dim3(16,2,B_), 256, SMB_S>>>(Wth, Wtl, D2h, D2l, out, nullptr, nullptr,
        C_, 0, sx, sv, N_, nullptr, X2f, ga, be, rm, rv, bt, nullptr);
}

// round 17
// speedup vs baseline: 3.3316x; 1.0544x over previous
#include <cuda_runtime.h>
#include <cuda_bf16.h>
#include <cuda_fp16.h>
#include <cstdint>

#define B_  16
#define C_  256
#define C2_ 128
#define N_  2048
#define BN_EPS 1e-5f
typedef __nv_bfloat16 bf16;

// ---------------- scratch (device globals) ---------------------------------
__device__ __align__(128) bf16 g_qTh[(size_t)B_*N_*C2_], g_qTl[(size_t)B_*N_*C2_];
__device__ __align__(128) bf16 g_xTh[(size_t)B_*N_*C2_], g_xTl[(size_t)B_*N_*C2_];
__device__ __align__(128) bf16 g_Wqh[C2_*C2_], g_Wql[C2_*C2_];
__device__ __align__(128) bf16 g_Wkh[C2_*C2_], g_Wkl[C2_*C2_];
__device__ __align__(128) bf16 g_Wvh[C_*C2_],  g_Wvl[C_*C2_];
__device__ __align__(128) bf16 g_Wth[C_*C_],   g_Wtl[C_*C_];
__device__ __align__(128) bf16 g_QTh[(size_t)B_*N_*C2_], g_QTl[(size_t)B_*N_*C2_];
__device__ __align__(128) bf16 g_KTh[(size_t)B_*N_*C2_], g_KTl[(size_t)B_*N_*C2_];
__device__ __align__(128) __half g_V16[(size_t)B_*C_*N_];
__device__ __align__(128) float g_X2f[(size_t)B_*C_*N_];
__device__ __align__(128) float g_rs[(size_t)B_*N_], g_rinv[(size_t)B_*N_];
__device__ __align__(128) bf16 g_PTh[(size_t)B_*N_*N_], g_PTl[(size_t)B_*N_*N_];
__device__ __align__(128) __half g_S16[(size_t)B_*N_*N_];
__device__ __align__(128) bf16 g_D2h[(size_t)B_*N_*C_], g_D2l[(size_t)B_*N_*C_];

// ---------------- helpers --------------------------------------------------
__device__ __forceinline__ uint32_t smem_u32(const void* p) {
    uint32_t a;
    asm("{ .reg .u64 t; cvta.to.shared.u64 t, %1; cvt.u32.u64 %0, t; }" : "=r"(a) : "l"(p));
    return a;
}
#define SWZ64(x) ((x) ^ (((x) >> 3) & 0x30))
#define CP_COMMIT() asm volatile("cp.async.commit_group;" ::: "memory")
#define CP_WAIT1()  asm volatile("cp.async.wait_group 1;" ::: "memory")
#define CP_WAIT0()  asm volatile("cp.async.wait_group 0;" ::: "memory")

__device__ __forceinline__ void cp16(uint32_t dst, const void* src) {
    asm volatile("cp.async.cg.shared.global [%0], [%1], 16;" :: "r"(dst), "l"(src));
}
__device__ __forceinline__ void ldsm4(uint32_t* r, uint32_t a) {
    asm volatile("ldmatrix.sync.aligned.m8n8.x4.shared.b16 {%0,%1,%2,%3}, [%4];"
        : "=r"(r[0]), "=r"(r[1]), "=r"(r[2]), "=r"(r[3]) : "r"(a));
}
__device__ __forceinline__ void ldsm2(uint32_t* r, uint32_t a) {
    asm volatile("ldmatrix.sync.aligned.m8n8.x2.shared.b16 {%0,%1}, [%2];"
        : "=r"(r[0]), "=r"(r[1]) : "r"(a));
}
template<int HALF>
__device__ __forceinline__ void mma16816(float* d, const uint32_t* a, const uint32_t* b) {
    if (HALF)
        asm volatile("mma.sync.aligned.m16n8k16.row.col.f32.f16.f16.f32 "
            "{%0,%1,%2,%3}, {%4,%5,%6,%7}, {%8,%9}, {%0,%1,%2,%3};"
            : "+f"(d[0]), "+f"(d[1]), "+f"(d[2]), "+f"(d[3])
            : "r"(a[0]), "r"(a[1]), "r"(a[2]), "r"(a[3]), "r"(b[0]), "r"(b[1]));
    else
        asm volatile("mma.sync.aligned.m16n8k16.row.col.f32.bf16.bf16.f32 "
            "{%0,%1,%2,%3}, {%4,%5,%6,%7}, {%8,%9}, {%0,%1,%2,%3};"
            : "+f"(d[0]), "+f"(d[1]), "+f"(d[2]), "+f"(d[3])
            : "r"(a[0]), "r"(a[1]), "r"(a[2]), "r"(a[3]), "r"(b[0]), "r"(b[1]));
}
__device__ __forceinline__ uint32_t pk(float a, float b) {
    __nv_bfloat162 t = __floats2bfloat162_rn(a, b);
    return *reinterpret_cast<uint32_t*>(&t);
}

// ---------------- warp-MMA GEMM --------------------------------------------
// C[M, Np] = A[M,K] * B[Np,K]^T, K-major 16-bit operands.
// SPLIT=1: hi/lo pairs, 3-term split product. Tile 128x128, Kc=32,
// 3-buffer cp.async pipeline (single sync/iter), 8 warps of 64x32, 2 CTAs/SM.
// EPI: 5 final relu(bn)+x2 | 7 E: exp + transposed hi/lo + rowsums
//      11 swapped XR: D2^T = split(x2f - acc), transpose-store
//      12 fused projections (flat grid: QK split-out / V16 / X2f)
template<int EPI, int SPLIT, int HALF>
__global__ __launch_bounds__(256, 2)
void mmk(const bf16* __restrict__ Ah, const bf16* __restrict__ Al,
         const bf16* __restrict__ Bh, const bf16* __restrict__ Bl,
         float* __restrict__ Cf, bf16* __restrict__ Ch, bf16* __restrict__ Cl,
         int Kdim, size_t sA, size_t sB, size_t sC, int ldC,
         const float* __restrict__ bias, const float* __restrict__ x2f,
         const float* __restrict__ ga, const float* __restrict__ be,
         const float* __restrict__ rm, const float* __restrict__ rv,
         const float* __restrict__ bt, float* __restrict__ rsum)
{
    constexpr int STG  = SPLIT ? 32768 : 16384;
    constexpr int BOFF = SPLIT ? 16384 : 8192;

    extern __shared__ __align__(128) char smem[];
    const uint32_t sb = smem_u32(smem);
    const int tid = threadIdx.x, wid = tid >> 5, lane = tid & 31;
    const int wm = wid & 1, wn = wid >> 1;
    const size_t rb = (size_t)Kdim * 2;

    int bx, by, bz, op12 = 0;
    if (EPI == 12) {
        int bid = blockIdx.x;
        if (bid < 512) { op12 = 0; bz = bid >> 4; by = bid & 15; bx = 0; }
        else { op12 = 1; int sub = bid - 512; bz = sub >> 5; int r = sub & 31; bx = r >> 1; by = r & 1; }
    } else { bx = blockIdx.x; by = blockIdx.y; bz = blockIdx.z; }
    const int bsel = bz & 15;

    const char *gAh, *gAl = nullptr, *gBh, *gBl = nullptr;
    if (EPI == 12) {
        if (op12 == 0) {
            const bf16* axh = (bz < 16) ? g_qTh : g_xTh;
            const bf16* axl = (bz < 16) ? g_qTl : g_xTl;
            gAh = (const char*)(axh + (size_t)bsel * ((size_t)N_*C2_)) + (size_t)(by * 128) * rb;
            gAl = (const char*)(axl + (size_t)bsel * ((size_t)N_*C2_)) + (size_t)(by * 128) * rb;
            gBh = (const char*)((bz < 16) ? g_Wqh : g_Wkh);
            gBl = (const char*)((bz < 16) ? g_Wql : g_Wkl);
        } else {
            gAh = (const char*)g_Wvh + (size_t)(by * 128) * rb;
            gAl = (const char*)g_Wvl + (size_t)(by * 128) * rb;
            const bf16* bxh = (bz < 16) ? g_qTh : g_xTh;
            const bf16* bxl = (bz < 16) ? g_qTl : g_xTl;
            gBh = (const char*)(bxh + (size_t)bsel * ((size_t)N_*C2_)) + (size_t)(bx * 128) * rb;
            gBl = (const char*)(bxl + (size_t)bsel * ((size_t)N_*C2_)) + (size_t)(bx * 128) * rb;
        }
    } else {
        gAh = (const char*)(Ah + bz * sA) + (size_t)(by * 128) * rb;
        gBh = (const char*)(Bh + bz * sB) + (size_t)(bx * 128) * rb;
        if (SPLIT) {
            gAl = (const char*)(Al + bz * sA) + (size_t)(by * 128) * rb;
            gBl = (const char*)(Bl + bz * sB) + (size_t)(bx * 128) * rb;
        }
    }

    float acc[4][4][4];
    #pragma unroll
    for (int i = 0; i < 4; i++)
        #pragma unroll
        for (int j = 0; j < 4; j++)
            #pragma unroll
            for (int k = 0; k < 4; k++) acc[i][j][k] = 0.f;

    const int NC = Kdim >> 5;

    auto load_stage = [&](int s, int chunk) {
        const uint32_t base = sb + s * STG;
        const size_t cb = (size_t)chunk * 64;
        #pragma unroll
        for (int j = 0; j < 2; j++) {
            int idx = j * 256 + tid;
            int r = idx >> 2, c = (idx & 3) * 16;
            uint32_t off = SWZ64(r * 64 + c);
            size_t go = (size_t)r * rb + cb + c;
            cp16(base + off,        gAh + go);
            cp16(base + BOFF + off, gBh + go);
            if (SPLIT) {
                cp16(base + 8192 + off,  gAl + go);
                cp16(base + 24576 + off, gBl + go);
            }
        }
        CP_COMMIT();
    };

    load_stage(0, 0);
    load_stage(1, 1);

    for (int i = 0; i < NC; i++) {
        if (i + 1 < NC) { CP_WAIT1(); } else { CP_WAIT0(); }
        __syncthreads();
        if (i + 2 < NC) load_stage((i + 2) % 3, i + 2);   // buffer (i-1)%3: free
        const uint32_t aB = sb + (i % 3) * STG, bB = aB + BOFF;
        #pragma unroll
        for (int ks = 0; ks < 2; ks++) {
            uint32_t bh[4][2], bl[4][2];
            #pragma unroll
            for (int na = 0; na < 4; na++) {
                int row = wn * 32 + na * 8 + (lane & 7);
                uint32_t off = SWZ64(row * 64 + ks * 32 + (((lane >> 3) & 1) * 16));
                ldsm2(bh[na], bB + off);
                if (SPLIT) ldsm2(bl[na], bB + 8192 + off);
            }
            #pragma unroll
            for (int ma = 0; ma < 4; ma++) {
                uint32_t ah[4], al[4];
                int row = wm * 64 + ma * 16 + (lane & 15);
                uint32_t off = SWZ64(row * 64 + ks * 32 + ((lane >> 4) * 16));
                ldsm4(ah, aB + off);
                if (SPLIT) ldsm4(al, aB + 8192 + off);
                #pragma unroll
                for (int na = 0; na < 4; na++) {
                    mma16816<HALF>(acc[ma][na], ah, bh[na]);
                    if (SPLIT) {
                        mma16816<HALF>(acc[ma][na], ah, bl[na]);
                        mma16816<HALF>(acc[ma][na], al, bh[na]);
                    }
                }
            }
        }
    }

    // ---------------- epilogue ----------------
    const int g = lane >> 2, t = lane & 3;
    const int mB = by * 128 + wm * 64;
    const int nB = bx * 128 + wn * 32;

    if (EPI == 7) {
        __syncthreads();
        uint32_t* stg = (uint32_t*)smem;   // stride 129
        #pragma unroll
        for (int ma = 0; ma < 4; ma++) {
            const int r0l = wm * 64 + ma * 16 + g;
            const int r1l = r0l + 8;
            float s0 = 0.f, s1 = 0.f;
            #pragma unroll
            for (int na = 0; na < 4; na++) {
                const int c0l = wn * 32 + na * 8 + 2 * t;
                const float* a = acc[ma][na];
                float p0 = __expf(fminf(a[0], 80.f));
                float p1 = __expf(fminf(a[1], 80.f));
                float p2 = __expf(fminf(a[2], 80.f));
                float p3 = __expf(fminf(a[3], 80.f));
                s0 += p0 + p1; s1 += p2 + p3;
                float h0 = __bfloat162float(__float2bfloat16(p0));
                float h1 = __bfloat162float(__float2bfloat16(p1));
                float h2 = __bfloat162float(__float2bfloat16(p2));
                float h3 = __bfloat162float(__float2bfloat16(p3));
                stg[r0l * 129 + c0l]     = pk(h0, p0 - h0);
                stg[r0l * 129 + c0l + 1] = pk(h1, p1 - h1);
                stg[r1l * 129 + c0l]     = pk(h2, p2 - h2);
                stg[r1l * 129 + c0l + 1] = pk(h3, p3 - h3);
            }
            s0 += __shfl_xor_sync(~0u, s0, 1); s0 += __shfl_xor_sync(~0u, s0, 2);
            s1 += __shfl_xor_sync(~0u, s1, 1); s1 += __shfl_xor_sync(~0u, s1, 2);
            if (t == 0) {
                atomicAdd(rsum + (size_t)bz * N_ + by * 128 + r0l, s0);
                atomicAdd(rsum + (size_t)bz * N_ + by * 128 + r1l, s1);
            }
        }
        __syncthreads();
        bf16* PThb = Ch + bz * sC;
        bf16* PTlb = Cl + bz * sC;
        const int rowBase = by * 128;
        const int colBase = bx * 128;
        #pragma unroll
        for (int it = 0; it < 16; it++) {
            const int cloc = wid * 16 + it;
            uint32_t u0 = stg[(lane * 4 + 0) * 129 + cloc];
            uint32_t u1 = stg[(lane * 4 + 1) * 129 + cloc];
            uint32_t u2 = stg[(lane * 4 + 2) * 129 + cloc];
            uint32_t u3 = stg[(lane * 4 + 3) * 129 + cloc];
            uint32_t hp0 = (u0 & 0xFFFFu) | (u1 << 16);
            uint32_t hp1 = (u2 & 0xFFFFu) | (u3 << 16);
            uint32_t lp0 = (u0 >> 16) | (u1 & 0xFFFF0000u);
            uint32_t lp1 = (u2 >> 16) | (u3 & 0xFFFF0000u);
            size_t off = (size_t)(colBase + cloc) * ldC + rowBase + lane * 4;
            *(uint2*)(PThb + off) = make_uint2(hp0, hp1);
            *(uint2*)(PTlb + off) = make_uint2(lp0, lp1);
        }
        return;
    }

    if (EPI == 11) {
        // acc[c_tile][m_tile] = XRf ; D2[m][c] = split(x2f[c][m] - acc), transposed store
        __syncthreads();
        uint32_t* stg = (uint32_t*)smem;   // [c_local][m_local] stride 129
        const float* x2b = x2f + (size_t)bz * ((size_t)C_ * N_);
        #pragma unroll
        for (int ma = 0; ma < 4; ma++) {
            const int r0l = wm * 64 + ma * 16 + g;   // local c
            const int r1l = r0l + 8;
            const int cG0 = by * 128 + r0l, cG1 = by * 128 + r1l;
            #pragma unroll
            for (int na = 0; na < 4; na++) {
                const int c0l = wn * 32 + na * 8 + 2 * t;   // local m
                const int mG = bx * 128 + c0l;
                const float* a = acc[ma][na];
                float2 x0 = *(const float2*)(x2b + (size_t)cG0 * N_ + mG);
                float2 x1 = *(const float2*)(x2b + (size_t)cG1 * N_ + mG);
                float v0 = x0.x - a[0], v1 = x0.y - a[1];
                float v2 = x1.x - a[2], v3 = x1.y - a[3];
                float h0 = __bfloat162float(__float2bfloat16(v0));
                float h1 = __bfloat162float(__float2bfloat16(v1));
                float h2 = __bfloat162float(__float2bfloat16(v2));
                float h3 = __bfloat162float(__float2bfloat16(v3));
                stg[r0l * 129 + c0l]     = pk(h0, v0 - h0);
                stg[r0l * 129 + c0l + 1] = pk(h1, v1 - h1);
                stg[r1l * 129 + c0l]     = pk(h2, v2 - h2);
                stg[r1l * 129 + c0l + 1] = pk(h3, v3 - h3);
            }
        }
        __syncthreads();
        bf16* Dhb = Ch + bz * sC;
        bf16* Dlb = Cl + bz * sC;
        const int cB0 = by * 128, mB0 = bx * 128;
        #pragma unroll
        for (int it = 0; it < 16; it++) {
            const int mloc = wid * 16 + it;
            uint32_t u0 = stg[(lane * 4 + 0) * 129 + mloc];
            uint32_t u1 = stg[(lane * 4 + 1) * 129 + mloc];
            uint32_t u2 = stg[(lane * 4 + 2) * 129 + mloc];
            uint32_t u3 = stg[(lane * 4 + 3) * 129 + mloc];
            uint32_t hp0 = (u0 & 0xFFFFu) | (u1 << 16);
            uint32_t hp1 = (u2 & 0xFFFFu) | (u3 << 16);
            uint32_t lp0 = (u0 >> 16) | (u1 & 0xFFFF0000u);
            uint32_t lp1 = (u2 >> 16) | (u3 & 0xFFFF0000u);
            size_t off = (size_t)(mB0 + mloc) * C_ + cB0 + lane * 4;
            *(uint2*)(Dhb + off) = make_uint2(hp0, hp1);
            *(uint2*)(Dlb + off) = make_uint2(lp0, lp1);
        }
        return;
    }

    if (EPI == 12) {
        if (op12 == 0) {
            bf16* Oh = ((bz < 16) ? g_QTh : g_KTh) + (size_t)bsel * ((size_t)N_*C2_);
            bf16* Ol = ((bz < 16) ? g_QTl : g_KTl) + (size_t)bsel * ((size_t)N_*C2_);
            #pragma unroll
            for (int ma = 0; ma < 4; ma++) {
                const int r0 = mB + ma * 16 + g, r1 = r0 + 8;
                #pragma unroll
                for (int na = 0; na < 4; na++) {
                    const int c0 = nB + na * 8 + 2 * t;
                    const float* a = acc[ma][na];
                    const size_t o0 = (size_t)r0 * C2_ + c0;
                    const size_t o1 = (size_t)r1 * C2_ + c0;
                    float h0 = __bfloat162float(__float2bfloat16(a[0]));
                    float h1 = __bfloat162float(__float2bfloat16(a[1]));
                    float h2 = __bfloat162float(__float2bfloat16(a[2]));
                    float h3 = __bfloat162float(__float2bfloat16(a[3]));
                    *(uint32_t*)(Oh + o0) = pk(h0, h1);
                    *(uint32_t*)(Ol + o0) = pk(a[0] - h0, a[1] - h1);
                    *(uint32_t*)(Oh + o1) = pk(h2, h3);
                    *(uint32_t*)(Ol + o1) = pk(a[2] - h2, a[3] - h3);
                }
            }
        } else if (bz < 16) {
            __half* Ob = g_V16 + (size_t)bsel * ((size_t)C_*N_);
            #pragma unroll
            for (int ma = 0; ma < 4; ma++) {
                const int r0 = mB + ma * 16 + g, r1 = r0 + 8;
                float p0 = bias[r0], p1 = bias[r1];
                #pragma unroll
                for (int na = 0; na < 4; na++) {
                    const int c0 = nB + na * 8 + 2 * t;
                    const float* a = acc[ma][na];
                    *(__half2*)(Ob + (size_t)r0 * N_ + c0) = __floats2half2_rn(a[0] + p0, a[1] + p0);
                    *(__half2*)(Ob + (size_t)r1 * N_ + c0) = __floats2half2_rn(a[2] + p1, a[3] + p1);
                }
            }
        } else {
            float* Ob = g_X2f + (size_t)bsel * ((size_t)C_*N_);
            #pragma unroll
            for (int ma = 0; ma < 4; ma++) {
                const int r0 = mB + ma * 16 + g, r1 = r0 + 8;
                float p0 = bias[r0], p1 = bias[r1];
                #pragma unroll
                for (int na = 0; na < 4; na++) {
                    const int c0 = nB + na * 8 + 2 * t;
                    const float* a = acc[ma][na];
                    *(float2*)(Ob + (size_t)r0 * N_ + c0) = make_float2(a[0] + p0, a[1] + p0);
                    *(float2*)(Ob + (size_t)r1 * N_ + c0) = make_float2(a[2] + p1, a[3] + p1);
                }
            }
        }
        return;
    }

    // EPI 5: final relu(bn(acc+bt)) + x2f
    float* Cfb = Cf + bz * sC;
    const float* x2b = x2f + bz * sC;
    #pragma unroll
    for (int ma = 0; ma < 4; ma++) {
        const int r0 = mB + ma * 16 + g;
        const int r1 = r0 + 8;
        float iv0 = ga[r0] * rsqrtf(rv[r0] + BN_EPS);
        float sh0 = be[r0] - rm[r0] * iv0, bo0 = bt[r0];
        float iv1 = ga[r1] * rsqrtf(rv[r1] + BN_EPS);
        float sh1 = be[r1] - rm[r1] * iv1, bo1 = bt[r1];
        #pragma unroll
        for (int na = 0; na < 4; na++) {
            const int c0 = nB + na * 8 + 2 * t;
            const float* a = acc[ma][na];
            const size_t o0 = (size_t)r0 * ldC + c0;
            const size_t o1 = (size_t)r1 * ldC + c0;
            float2 x0 = *(const float2*)(x2b + o0);
            float2 x1 = *(const float2*)(x2b + o1);
            float2 w0, w1;
            w0.x = fmaxf((a[0] + bo0) * iv0 + sh0, 0.f) + x0.x;
            w0.y = fmaxf((a[1] + bo0) * iv0 + sh0, 0.f) + x0.y;
            w1.x = fmaxf((a[2] + bo1) * iv1 + sh1, 0.f) + x1.x;
            w1.y = fmaxf((a[3] + bo1) * iv1 + sh1, 0.f) + x1.y;
            *(float2*)(Cfb + o0) = w0;
            *(float2*)(Cfb + o1) = w1;
        }
    }
}

// ---------------- aux kernels ----------------------------------------------
__global__ void splitw_all(const float* __restrict__ Wq, const float* __restrict__ Wk,
                           const float* __restrict__ Wv, const float* __restrict__ Wt)
{
    int i = blockIdx.x * 256 + threadIdx.x;
    const float* src; bf16 *h, *l; int off;
    if (i < 16384)      { src = Wq; h = g_Wqh; l = g_Wql; off = i; }
    else if (i < 32768) { src = Wk; h = g_Wkh; l = g_Wkl; off = i - 16384; }
    else if (i < 65536) { src = Wv; h = g_Wvh; l = g_Wvl; off = i - 32768; }
    else                { src = Wt; h = g_Wth; l = g_Wtl; off = i - 65536; }
    float v = src[off];
    bf16 hv = __float2bfloat16(v);
    h[off] = hv;
    l[off] = __float2bfloat16(v - __bfloat162float(hv));
}

__global__ void tsplit2(const float* __restrict__ q, const float* __restrict__ x)
{
    __shared__ float sm[32][33];
    const int bz = blockIdx.z;
    const int b = bz & 15;
    const float* ip = ((bz < 16) ? q : x) + (size_t)b * C2_ * N_;
    bf16* oph = ((bz < 16) ? g_qTh : g_xTh) + (size_t)b * N_ * C2_;
    bf16* opl = ((bz < 16) ? g_qTl : g_xTl) + (size_t)b * N_ * C2_;
    const int n0 = blockIdx.x * 32, c0 = blockIdx.y * 32;
    const int r = threadIdx.x >> 5, c = threadIdx.x & 31;
    #pragma unroll
    for (int k = 0; k < 4; k++)
        sm[r + 8*k][c] = ip[(size_t)(c0 + r + 8*k) * N_ + n0 + c];
    __syncthreads();
    #pragma unroll
    for (int k = 0; k < 4; k++) {
        float v = sm[c][r + 8*k];
        bf16 hv = __float2bfloat16(v);
        size_t o = (size_t)(n0 + r + 8*k) * C2_ + c0 + c;
        oph[o] = hv;
        opl[o] = __float2bfloat16(v - __bfloat162float(hv));
    }
}

__global__ void zero_k(float* p, int n)
{
    int i = blockIdx.x * 256 + threadIdx.x;
    if (i < n) p[i] = 0.f;
}

__global__ void rinvk(const float* __restrict__ rs, float* __restrict__ ri, int n)
{
    int i = blockIdx.x * 256 + threadIdx.x;
    if (i < n) ri[i] = 1.f / rs[i];
}

__global__ __launch_bounds__(256)
void normk(const bf16* __restrict__ pth, const bf16* __restrict__ ptl,
           const float* __restrict__ ri, __half* __restrict__ s16)
{
    const int wid = threadIdx.x >> 5, lane = threadIdx.x & 31;
    const size_t row = (size_t)blockIdx.x * 8 + wid;
    const bf16* ph = pth + row * N_;
    const bf16* pl = ptl + row * N_;
    const float* rv = ri + ((row >> 11) << 11);
    float v[64];
    float s = 0.f;
    #pragma unroll
    for (int k = 0; k < 8; k++) {
        int n0 = k * 256 + lane * 8;
        uint4 uh = *(const uint4*)(ph + n0);
        uint4 ul = *(const uint4*)(pl + n0);
        float4 r0 = *(const float4*)(rv + n0);
        float4 r1 = *(const float4*)(rv + n0 + 4);
        float rr[8];
        *(float4*)rr = r0; *(float4*)(rr + 4) = r1;
        const uint32_t* hw = (const uint32_t*)&uh;
        const uint32_t* lw = (const uint32_t*)&ul;
        #pragma unroll
        for (int j = 0; j < 4; j++) {
            float2 hv = __bfloat1622float2(*(const __nv_bfloat162*)&hw[j]);
            float2 lv = __bfloat1622float2(*(const __nv_bfloat162*)&lw[j]);
            float a = (hv.x + lv.x) * rr[2*j];
            float b = (hv.y + lv.y) * rr[2*j + 1];
            v[k*8 + 2*j] = a; v[k*8 + 2*j + 1] = b;
            s += a + b;
        }
    }
    #pragma unroll
    for (int o = 16; o > 0; o >>= 1) s += __shfl_xor_sync(~0u, s, o);
    const float inv = 1.f / (1e-9f + s);
    __half* op = s16 + row * N_;
    #pragma unroll
    for (int k = 0; k < 8; k++) {
        int n0 = k * 256 + lane * 8;
        __half2 h4[4];
        #pragma unroll
        for (int j = 0; j < 4; j++)
            h4[j] = __floats2half2_rn(v[k*8 + 2*j] * inv, v[k*8 + 2*j + 1] * inv);
        *(uint4*)(op + n0) = *(uint4*)h4;
    }
}

// ---------------- launcher -------------------------------------------------
extern "C" void kernel_launch(void* const* d_in, const int* in_sizes, int n_in,
                              void* d_out, int out_size)
{
    const float* q  = (const float*)d_in[0];
    const float* x  = (const float*)d_in[1];
    const float* Wq = (const float*)d_in[2];
    const float* Wk = (const float*)d_in[3];
    const float* Wv = (const float*)d_in[4];
    const float* bv = (const float*)d_in[5];
    const float* Wt = (const float*)d_in[6];
    const float* bt = (const float*)d_in[7];
    const float* ga = (const float*)d_in[8];
    const float* be = (const float*)d_in[9];
    const float* rm = (const float*)d_in[10];
    const float* rv = (const float*)d_in[11];
    float* out = (float*)d_out;

    #define SYM(T, p, s) T* p; cudaGetSymbolAddress((void**)&p, s)
    SYM(bf16, Wth, g_Wth); SYM(bf16, Wtl, g_Wtl);
    SYM(bf16, QTh, g_QTh); SYM(bf16, QTl, g_QTl);
    SYM(bf16, KTh, g_KTh); SYM(bf16, KTl, g_KTl);
    SYM(__half, V16, g_V16);
    SYM(float, X2f, g_X2f);
    SYM(float, rs, g_rs); SYM(float, ri, g_rinv);
    SYM(bf16, PTh, g_PTh); SYM(bf16, PTl, g_PTl);
    SYM(__half, S16, g_S16);
    SYM(bf16, D2h, g_D2h); SYM(bf16, D2l, g_D2l);
    #undef SYM

    const int SMB_S  = 3 * 32768;     // 98304: split kernels
    const int SMB_T  = 128 * 129 * 4; // 66048: XR swapped (pipeline 48K + staging 64.5K)
    cudaFuncSetAttribute(mmk<5,1,0>,  cudaFuncAttributeMaxDynamicSharedMemorySize, SMB_S);
    cudaFuncSetAttribute(mmk<7,1,0>,  cudaFuncAttributeMaxDynamicSharedMemorySize, SMB_S);
    cudaFuncSetAttribute(mmk<12,1,0>, cudaFuncAttributeMaxDynamicSharedMemorySize, SMB_S);
    cudaFuncSetAttribute(mmk<11,0,1>, cudaFuncAttributeMaxDynamicSharedMemorySize, SMB_T);

    const size_t s2 = (size_t)N_ * C2_;
    const size_t sv = (size_t)C_ * N_;
    const size_t sx = (size_t)N_ * C_;
    const size_t se = (size_t)N_ * N_;

    zero_k<<<(B_*N_+255)/256, 256>>>(rs, B_*N_);
    splitw_all<<<512, 256>>>(Wq, Wk, Wv, Wt);
    tsplit2<<<dim3(N_/32, C2_/32, 2*B_), 256>>>(q, x);

    // fused projections: [0,512) QK -> QT/KT ; [512,1536) -> V16 / X2f
    mmk<12,1,0><<<1536, 256, SMB_S>>>(nullptr, nullptr, nullptr, nullptr,
        nullptr, nullptr, nullptr, C2_, 0, 0, 0, 0,
        bv, nullptr, nullptr, nullptr, nullptr, nullptr, nullptr, nullptr);
    // E-GEMM -> PT hi/lo + rowsums
    mmk<7,1,0><<<dim3(16,16,B_), 256, SMB_S>>>(QTh, QTl, KTh, KTl, nullptr, PTh, PTl,
        C2_, s2, s2, se, N_, nullptr, nullptr, nullptr, nullptr, nullptr, nullptr, nullptr, rs);
    // rinv; fully-normalized S16 (fp16)
    rinvk<<<(B_*N_+255)/256, 256>>>(rs, ri, B_*N_);
    normk<<<B_*N_/8, 256>>>(PTh, PTl, ri, S16);
    // swapped XR GEMM (fp16): XRf[c][m] = V16*S16^T ; D2[m][c] = split(X2f - acc)
    mmk<11,0,1><<<dim3(16,2,B_), 256, SMB_T>>>((const bf16*)V16, nullptr, (const bf16*)S16, nullptr,
        nullptr, D2h, D2l, N_, sv, se, sx, C_, nullptr, X2f, nullptr, nullptr, nullptr, nullptr, nullptr, nullptr);
    // out[c][n] = relu(bn(Wt*D2 + bt)) + X2f
    mmk<5,1,0><<<dim3(16,2,B_), 256, SMB_S>>>(Wth, Wtl, D2h, D2l, out, nullptr, nullptr,
        C_, 0, sx, sv, N_, nullptr, X2f, ga, be, rm, rv, bt, nullptr);
}